// round 6
// baseline (speedup 1.0000x reference)
#include <cuda_runtime.h>
#include <cuda_bf16.h>
#include <math.h>
#include <stdint.h>

#define BATCH   4
#define SEQ     2048
#define DM      768
#define DI      1536
#define DSTATE  64
#define DTR     48
#define XPD     (DTR + 2*DSTATE)   // 176
#define XPDP    256                // padded rows for x_proj weight
#define DTKP    64                 // padded K for dt GEMM (48 -> 64)
#define NTOK    (BATCH*SEQ)        // 8192

typedef __nv_bfloat16 bf16;

// ---------------- scratch (static device globals; zero-initialized) ---------
__device__ __align__(256) float g_xz   [(size_t)NTOK * 2*DI];
__device__ __align__(256) float g_uT   [(size_t)BATCH*DI*SEQ];
__device__ __align__(256) float g_xdbl [(size_t)NTOK * XPD];
__device__ __align__(256) float g_dtT  [(size_t)BATCH*DI*SEQ];
__device__ __align__(256) float g_yT   [(size_t)BATCH*DI*SEQ];

// bf16 hi/lo operand buffers in TILED layout (pads stay zero: never written)
__device__ __align__(256) bf16 g_x0h[(size_t)NTOK*DM],  g_x0l[(size_t)NTOK*DM];
__device__ __align__(256) bf16 g_x1h[(size_t)NTOK*DM],  g_x1l[(size_t)NTOK*DM];
__device__ __align__(256) bf16 g_xch[(size_t)NTOK*DI],  g_xcl[(size_t)NTOK*DI];
__device__ __align__(256) bf16 g_dah[(size_t)NTOK*DTKP],g_dal[(size_t)NTOK*DTKP];
__device__ __align__(256) bf16 g_gth[(size_t)NTOK*DI],  g_gtl[(size_t)NTOK*DI];
__device__ __align__(256) bf16 g_wih[(size_t)2*2*DI*DM], g_wil[(size_t)2*2*DI*DM];
__device__ __align__(256) bf16 g_wxh[(size_t)2*XPDP*DI], g_wxl[(size_t)2*XPDP*DI];
__device__ __align__(256) bf16 g_wdh[(size_t)2*DI*DTKP], g_wdl[(size_t)2*DI*DTKP];
__device__ __align__(256) bf16 g_woh[(size_t)2*DM*DI],   g_wol[(size_t)2*DM*DI];

// ---------------- tiled layout ----------------
// 128-row x 32-col tiles of bf16 (4096 elems = 8KB, contiguous).
// Within tile: 64B rows, four 16B granules, granule g XOR-swizzled by (r>>1)&3.
// Element offset — byte-identical to the SMEM layout ldmatrix reads.
__device__ __forceinline__ size_t toff(int r, int c, int K) {
    return ((size_t)((r >> 7) * (K >> 5) + (c >> 5))) * 4096
         + (size_t)((r & 127) * 32
         + (((((c >> 3) & 3) ^ ((r >> 1) & 3)) << 3) | (c & 7)));
}

// ---------------- PTX helpers ----------------
__device__ __forceinline__ void split_bf(float x, bf16& h, bf16& l) {
    h = __float2bfloat16(x);
    l = __float2bfloat16(x - __bfloat162float(h));
}

__device__ __forceinline__ void bulkcp(uint32_t dst, const void* src,
                                       uint32_t bytes, uint32_t mbar) {
    asm volatile(
        "cp.async.bulk.shared::cluster.global.mbarrier::complete_tx::bytes "
        "[%0], [%1], %2, [%3];"
        :: "r"(dst), "l"(src), "r"(bytes), "r"(mbar) : "memory");
}

#define MBAR_INIT(addr, cnt) \
    asm volatile("mbarrier.init.shared.b64 [%0], %1;" :: "r"(addr), "r"(cnt) : "memory")
#define MBAR_INVAL(addr) \
    asm volatile("mbarrier.inval.shared.b64 [%0];" :: "r"(addr) : "memory")
#define MBAR_EXPECT_TX(addr, bytes) \
    asm volatile("mbarrier.arrive.expect_tx.shared.b64 _, [%0], %1;" \
        :: "r"(addr), "r"((uint32_t)(bytes)) : "memory")
#define MBAR_ARRIVE(addr) \
    asm volatile("mbarrier.arrive.shared.b64 _, [%0];" :: "r"(addr) : "memory")

#define MBAR_WAIT(mbar_addr, phase_parity) do { \
    uint32_t _mbar = (uint32_t)(mbar_addr); \
    uint32_t _parity = (uint32_t)(phase_parity); \
    uint32_t _done; \
    asm volatile("{\n\t.reg .pred p;\n\t" \
        "mbarrier.try_wait.parity.acquire.cta.shared::cta.b64 p, [%1], %2;\n\t" \
        "selp.b32 %0, 1, 0, p;\n\t}" \
        : "=r"(_done) : "r"(_mbar), "r"(_parity) : "memory"); \
    if (!_done) { \
        asm volatile("{\n\t.reg .pred P1;\n\t" \
            "WAIT_LOOP_%=:\n\t" \
            "mbarrier.try_wait.parity.acquire.cta.shared::cta.b64 P1, [%0], %1, 0x989680;\n\t" \
            "@P1 bra.uni WAIT_DONE_%=;\n\t" \
            "bra.uni WAIT_LOOP_%=;\n\t" \
            "WAIT_DONE_%=:\n\t}" \
            :: "r"(_mbar), "r"(_parity) : "memory"); \
    } \
} while(0)

__device__ __forceinline__ void ldsm_x4(uint32_t& r0, uint32_t& r1, uint32_t& r2, uint32_t& r3, uint32_t a) {
    asm volatile("ldmatrix.sync.aligned.m8n8.x4.shared.b16 {%0,%1,%2,%3}, [%4];"
                 : "=r"(r0), "=r"(r1), "=r"(r2), "=r"(r3) : "r"(a));
}
__device__ __forceinline__ void ldsm_x2(uint32_t& r0, uint32_t& r1, uint32_t a) {
    asm volatile("ldmatrix.sync.aligned.m8n8.x2.shared.b16 {%0,%1}, [%2];"
                 : "=r"(r0), "=r"(r1) : "r"(a));
}
__device__ __forceinline__ void mma_bf16(float* d, const uint32_t* a, const uint32_t* b) {
    asm volatile(
        "mma.sync.aligned.m16n8k16.row.col.f32.bf16.bf16.f32 "
        "{%0,%1,%2,%3}, {%4,%5,%6,%7}, {%8,%9}, {%0,%1,%2,%3};"
        : "+f"(d[0]), "+f"(d[1]), "+f"(d[2]), "+f"(d[3])
        : "r"(a[0]), "r"(a[1]), "r"(a[2]), "r"(a[3]), "r"(b[0]), "r"(b[1]));
}

// ---------------- bulk-copy bf16x3 GEMM ----------------
// C[M,N] = (Ah+Al)[M,K] * (Bh+Bl)[N,K]^T, operands in tiled layout.
// CTA tile 128x128, 256 thr (8 warps 2x4), warp tile 64x32, k-chunk 32.
// 6-stage mbarrier ring, 1 cp.async.bulk per 8KB tile (4 per stage).
// EPI 0: f32 C.  EPI 1: softplus(acc+bias[gc]) -> dtT[b][gc][t].
// EPI 2: f32 C (cols<N) + (hi,lo) of cols<DTR into tiled dtA (K=64).
// EPI 3: (hi,lo) into tiled Ho/Lo with K=Kho.
#define NST 6
#define STG 32768
#define AUXB (NST*STG)            // 196608
#define SMEMDYN (AUXB + 128)

template<int EPI>
__global__ __launch_bounds__(256)
void tc_gemm(const bf16* __restrict__ Ah, const bf16* __restrict__ Al,
             const bf16* __restrict__ Bh, const bf16* __restrict__ Bl,
             const float* __restrict__ bias,
             float* __restrict__ C, int N,
             bf16* __restrict__ Ho, bf16* __restrict__ Lo, int Kho,
             int K)
{
    extern __shared__ __align__(1024) uint8_t sm[];
    const uint32_t smb = (uint32_t)__cvta_generic_to_shared(sm);
    const int tid = threadIdx.x, lane = tid & 31, wid = tid >> 5;
    const int warpM = wid >> 2, warpN = wid & 3;
    const int rowBlk = blockIdx.y * 128, colBlk = blockIdx.x * 128;
    const int fr = lane >> 2, fc = lane & 3;
    const int nk = K >> 5;

    const bf16* pAh = Ah + (size_t)blockIdx.y * nk * 4096;
    const bf16* pAl = Al + (size_t)blockIdx.y * nk * 4096;
    const bf16* pBh = Bh + (size_t)blockIdx.x * nk * 4096;
    const bf16* pBl = Bl + (size_t)blockIdx.x * nk * 4096;

    if (tid == 0) {
#pragma unroll
        for (int s = 0; s < NST; s++) {
            MBAR_INIT(smb + AUXB + s * 8, 1);        // full
            MBAR_INIT(smb + AUXB + 48 + s * 8, 8);   // empty
        }
    }
    __syncthreads();

    if (tid == 0) {
        int pre = nk < NST ? nk : NST;
        for (int s = 0; s < pre; s++) {
            uint32_t mb = smb + AUXB + s * 8;
            MBAR_EXPECT_TX(mb, 4 * 8192);
            uint32_t d = smb + s * STG;
            bulkcp(d,         pAh + (size_t)s * 4096, 8192, mb);
            bulkcp(d + 8192,  pAl + (size_t)s * 4096, 8192, mb);
            bulkcp(d + 16384, pBh + (size_t)s * 4096, 8192, mb);
            bulkcp(d + 24576, pBl + (size_t)s * 4096, 8192, mb);
        }
    }

    float acc[4][4][4];
#pragma unroll
    for (int mt = 0; mt < 4; mt++)
#pragma unroll
        for (int nt = 0; nt < 4; nt++)
#pragma unroll
            for (int q = 0; q < 4; q++) acc[mt][nt][q] = 0.f;

    // fragment addressing (proven round-4 layout: 64B rows, granule XOR swizzle)
    uint32_t arow[4], asw[4], brow[4], bsw[4];
#pragma unroll
    for (int mt = 0; mt < 4; mt++) {
        int r = warpM * 64 + mt * 16 + (lane & 15);
        arow[mt] = r * 64; asw[mt] = (r >> 1) & 3;
    }
#pragma unroll
    for (int nt = 0; nt < 4; nt++) {
        int n = warpN * 32 + nt * 8 + (lane & 7);
        brow[nt] = n * 64; bsw[nt] = (n >> 1) & 3;
    }
    const int akg = lane >> 4;
    const int bkg = (lane >> 3) & 1;

    for (int c = 0; c < nk; c++) {
        const int st = c % NST;
        const int ph = (c / NST) & 1;
        MBAR_WAIT(smb + AUXB + st * 8, ph);

        const uint32_t sA = smb + st * STG;
        const uint32_t sB = sA + 16384;
#pragma unroll
        for (int ks = 0; ks < 2; ks++) {
            uint32_t bh[4][2], bl[4][2];
#pragma unroll
            for (int nt = 0; nt < 4; nt++) {
                uint32_t off = brow[nt] + (((ks * 2 + bkg) ^ bsw[nt]) << 4);
                ldsm_x2(bh[nt][0], bh[nt][1], sB + off);
                ldsm_x2(bl[nt][0], bl[nt][1], sB + 8192 + off);
            }
#pragma unroll
            for (int mt = 0; mt < 4; mt++) {
                uint32_t off = arow[mt] + (((ks * 2 + akg) ^ asw[mt]) << 4);
                uint32_t ah[4], al[4];
                ldsm_x4(ah[0], ah[1], ah[2], ah[3], sA + off);
                ldsm_x4(al[0], al[1], al[2], al[3], sA + 8192 + off);
#pragma unroll
                for (int nt = 0; nt < 4; nt++) {
                    mma_bf16(acc[mt][nt], ah, bh[nt]);
                    mma_bf16(acc[mt][nt], ah, bl[nt]);
                    mma_bf16(acc[mt][nt], al, bh[nt]);
                }
            }
        }
        if (lane == 0) MBAR_ARRIVE(smb + AUXB + 48 + st * 8);

        if (tid == 0 && c + NST < nk) {
            MBAR_WAIT(smb + AUXB + 48 + st * 8, ph);   // all 8 warps done round c/NST
            uint32_t mb = smb + AUXB + st * 8;
            MBAR_EXPECT_TX(mb, 4 * 8192);
            uint32_t d = smb + st * STG;
            size_t o = (size_t)(c + NST) * 4096;
            bulkcp(d,         pAh + o, 8192, mb);
            bulkcp(d + 8192,  pAl + o, 8192, mb);
            bulkcp(d + 16384, pBh + o, 8192, mb);
            bulkcp(d + 24576, pBl + o, 8192, mb);
        }
    }

    // ---- epilogue (register accumulators) ----
#pragma unroll
    for (int mt = 0; mt < 4; mt++) {
#pragma unroll
        for (int nt = 0; nt < 4; nt++) {
            int gr0 = rowBlk + warpM * 64 + mt * 16 + fr;
            int gc  = colBlk + warpN * 32 + nt * 8 + 2 * fc;
            if (EPI == 0) {
                *(float2*)&C[(size_t)gr0 * N + gc] =
                    make_float2(acc[mt][nt][0], acc[mt][nt][1]);
                *(float2*)&C[(size_t)(gr0 + 8) * N + gc] =
                    make_float2(acc[mt][nt][2], acc[mt][nt][3]);
            } else if (EPI == 1) {
                float bv0 = bias[gc], bv1 = bias[gc + 1];
#pragma unroll
                for (int h = 0; h < 2; h++) {
                    int gr = gr0 + h * 8;
                    int b = gr >> 11, t = gr & (SEQ - 1);
                    float v0 = acc[mt][nt][h * 2 + 0] + bv0;
                    float v1 = acc[mt][nt][h * 2 + 1] + bv1;
                    v0 = (v0 > 20.f) ? v0 : log1pf(__expf(v0));
                    v1 = (v1 > 20.f) ? v1 : log1pf(__expf(v1));
                    C[((size_t)b * DI + gc)     * SEQ + t] = v0;
                    C[((size_t)b * DI + gc + 1) * SEQ + t] = v1;
                }
            } else if (EPI == 2) {
#pragma unroll
                for (int h = 0; h < 2; h++) {
                    int gr = gr0 + h * 8;
                    float v0 = acc[mt][nt][h * 2 + 0];
                    float v1 = acc[mt][nt][h * 2 + 1];
                    if (gc < N) {
                        C[(size_t)gr * N + gc]     = v0;
                        C[(size_t)gr * N + gc + 1] = v1;
                    }
                    if (gc < DTR) {
                        bf16 h0, l0, h1, l1;
                        split_bf(v0, h0, l0); split_bf(v1, h1, l1);
                        size_t o = toff(gr, gc, DTKP);
                        *(uint32_t*)&Ho[o] = (uint32_t)__bfloat16_as_ushort(h0)
                                           | ((uint32_t)__bfloat16_as_ushort(h1) << 16);
                        *(uint32_t*)&Lo[o] = (uint32_t)__bfloat16_as_ushort(l0)
                                           | ((uint32_t)__bfloat16_as_ushort(l1) << 16);
                    }
                }
            } else {   // EPI 3
#pragma unroll
                for (int h = 0; h < 2; h++) {
                    int gr = gr0 + h * 8;
                    bf16 h0, l0, h1, l1;
                    split_bf(acc[mt][nt][h * 2 + 0], h0, l0);
                    split_bf(acc[mt][nt][h * 2 + 1], h1, l1);
                    size_t o = toff(gr, gc, Kho);
                    *(uint32_t*)&Ho[o] = (uint32_t)__bfloat16_as_ushort(h0)
                                       | ((uint32_t)__bfloat16_as_ushort(h1) << 16);
                    *(uint32_t*)&Lo[o] = (uint32_t)__bfloat16_as_ushort(l0)
                                       | ((uint32_t)__bfloat16_as_ushort(l1) << 16);
                }
            }
        }
    }

    __syncthreads();
    if (tid == 0) {
#pragma unroll
        for (int s = 0; s < NST; s++) {
            MBAR_INVAL(smb + AUXB + s * 8);
            MBAR_INVAL(smb + AUXB + 48 + s * 8);
        }
    }
}

// ---------------- f32 -> (hi, lo) bf16 split into tiled layout ----------------
__global__ __launch_bounds__(256)
void split_tiled(const float* __restrict__ in, size_t sstride, size_t dstride,
                 int rows, int cols, int K,
                 bf16* __restrict__ H, bf16* __restrict__ L)
{
    const float* src = in + (size_t)blockIdx.y * sstride;
    bf16* h = H + (size_t)blockIdx.y * dstride;
    bf16* l = L + (size_t)blockIdx.y * dstride;
    int i = blockIdx.x * 256 + threadIdx.x;
    if (i >= rows * cols) return;
    int r = i / cols, c = i - r * cols;
    float x = src[(size_t)r * cols + c];
    bf16 hh, ll; split_bf(x, hh, ll);
    size_t o = toff(r, c, K);
    h[o] = hh; l[o] = ll;
}

// ---------------- causal depthwise conv (K=4) + SiLU ----------------
__global__ __launch_bounds__(1024)
void conv_silu_kernel(const float* __restrict__ xz,
                      const float* __restrict__ cw, const float* __restrict__ cb,
                      bf16* __restrict__ xch, bf16* __restrict__ xcl,
                      float* __restrict__ uT)
{
    __shared__ float xs[35][33];
    __shared__ float ys[32][33];
    const int tx = threadIdx.x, ty = threadIdx.y;
    const int t0 = blockIdx.x * 32, d0 = blockIdx.y * 32, b = blockIdx.z;

    for (int r = ty; r < 35; r += 32) {
        int t = t0 - 3 + r;
        xs[r][tx] = (t >= 0) ? xz[((size_t)b * SEQ + t) * (2 * DI) + d0 + tx] : 0.f;
    }
    __syncthreads();

    const int d = d0 + tx;
    const float w0 = cw[d * 4 + 0], w1 = cw[d * 4 + 1],
                w2 = cw[d * 4 + 2], w3 = cw[d * 4 + 3];
    float acc = cb[d];
    acc = fmaf(w0, xs[ty + 0][tx], acc);
    acc = fmaf(w1, xs[ty + 1][tx], acc);
    acc = fmaf(w2, xs[ty + 2][tx], acc);
    acc = fmaf(w3, xs[ty + 3][tx], acc);
    float v = acc / (1.f + __expf(-acc));

    bf16 h, l; split_bf(v, h, l);
    size_t o = toff(b * SEQ + t0 + ty, d, DI);
    xch[o] = h; xcl[o] = l;
    ys[ty][tx] = v;
    __syncthreads();
    uT[((size_t)b * DI + d0 + ty) * SEQ + t0 + tx] = ys[tx][ty];
}

// ---------------- selective scan: one warp per (b, d) channel ----------------
__global__ __launch_bounds__(128)
void scan_kernel(const float* __restrict__ dtT, const float* __restrict__ uT,
                 const float* __restrict__ xdbl, const float* __restrict__ A_log,
                 float* __restrict__ yT)
{
    const int wid  = blockIdx.x * (blockDim.x >> 5) + (threadIdx.x >> 5);
    const int lane = threadIdx.x & 31;
    const int b = wid / DI;
    const int d = wid % DI;

    const float A0 = -__expf(A_log[(size_t)d * DSTATE + lane]);
    const float A1 = -__expf(A_log[(size_t)d * DSTATE + lane + 32]);
    float h0 = 0.f, h1 = 0.f;

    const float* dtp = dtT + ((size_t)b * DI + d) * SEQ;
    const float* up  = uT  + ((size_t)b * DI + d) * SEQ;
    float*       yp  = yT  + ((size_t)b * DI + d) * SEQ;

    for (int t0 = 0; t0 < SEQ; t0 += 32) {
        float dtc = dtp[t0 + lane];
        float uc  = up [t0 + lane];
        float ykeep = 0.f;
        const float* bc = xdbl + ((size_t)b * SEQ + t0) * XPD;
#pragma unroll 4
        for (int s = 0; s < 32; s++) {
            float dts = __shfl_sync(0xffffffffu, dtc, s);
            float us  = __shfl_sync(0xffffffffu, uc,  s);
            const float* row = bc + (size_t)s * XPD + DTR;
            float Bn0 = __ldg(row + lane);
            float Bn1 = __ldg(row + lane + 32);
            float Cn0 = __ldg(row + 64 + lane);
            float Cn1 = __ldg(row + 64 + lane + 32);
            float du = dts * us;
            h0 = fmaf(__expf(dts * A0), h0, du * Bn0);
            h1 = fmaf(__expf(dts * A1), h1, du * Bn1);
            float yv = fmaf(h0, Cn0, h1 * Cn1);
#pragma unroll
            for (int off = 16; off; off >>= 1)
                yv += __shfl_xor_sync(0xffffffffu, yv, off);
            if (lane == s) ykeep = yv;
        }
        yp[t0 + lane] = ykeep;
    }
}

// ---------------- gate: (y + D*u) * silu(z) -> tiled (hi, lo) bf16 ----------
__global__ __launch_bounds__(1024)
void gate_kernel(const float* __restrict__ yT, const float* __restrict__ uT,
                 const float* __restrict__ Dp, const float* __restrict__ xz,
                 bf16* __restrict__ gth, bf16* __restrict__ gtl)
{
    __shared__ float s[32][33];
    const int tx = threadIdx.x, ty = threadIdx.y;
    const int t0 = blockIdx.x * 32, d0 = blockIdx.y * 32, b = blockIdx.z;

    size_t idx = ((size_t)b * DI + d0 + ty) * SEQ + t0 + tx;
    s[ty][tx] = yT[idx] + Dp[d0 + ty] * uT[idx];
    __syncthreads();

    const int t = t0 + ty, d = d0 + tx;
    float z  = xz[((size_t)b * SEQ + t) * (2 * DI) + DI + d];
    float sz = z / (1.f + __expf(-z));
    float v  = s[tx][ty] * sz;
    bf16 h, l; split_bf(v, h, l);
    size_t o = toff(b * SEQ + t, d, DI);
    gth[o] = h; gtl[o] = l;
}

// ---------------- host ----------------
static inline int cdiv(int a, int b) { return (a + b - 1) / b; }

extern "C" void kernel_launch(void* const* d_in, const int* in_sizes, int n_in,
                              void* d_out, int out_size)
{
    const float* x    = (const float*)d_in[0];
    const float* Wi   = (const float*)d_in[1];
    const float* cw   = (const float*)d_in[2];
    const float* cb   = (const float*)d_in[3];
    const float* Wx   = (const float*)d_in[4];
    const float* Wdt  = (const float*)d_in[5];
    const float* bdt  = (const float*)d_in[6];
    const float* Alog = (const float*)d_in[7];
    const float* Dp   = (const float*)d_in[8];
    const float* Wo   = (const float*)d_in[9];

    float *p_xz, *p_uT, *p_xdbl, *p_dtT, *p_yT;
    cudaGetSymbolAddress((void**)&p_xz,   g_xz);
    cudaGetSymbolAddress((void**)&p_uT,   g_uT);
    cudaGetSymbolAddress((void**)&p_xdbl, g_xdbl);
    cudaGetSymbolAddress((void**)&p_dtT,  g_dtT);
    cudaGetSymbolAddress((void**)&p_yT,   g_yT);

    bf16 *x0h, *x0l, *x1h, *x1l, *xch, *xcl, *dah, *dal, *gth, *gtl;
    bf16 *wih, *wil, *wxh, *wxl, *wdh, *wdl, *woh, *wol;
    cudaGetSymbolAddress((void**)&x0h, g_x0h); cudaGetSymbolAddress((void**)&x0l, g_x0l);
    cudaGetSymbolAddress((void**)&x1h, g_x1h); cudaGetSymbolAddress((void**)&x1l, g_x1l);
    cudaGetSymbolAddress((void**)&xch, g_xch); cudaGetSymbolAddress((void**)&xcl, g_xcl);
    cudaGetSymbolAddress((void**)&dah, g_dah); cudaGetSymbolAddress((void**)&dal, g_dal);
    cudaGetSymbolAddress((void**)&gth, g_gth); cudaGetSymbolAddress((void**)&gtl, g_gtl);
    cudaGetSymbolAddress((void**)&wih, g_wih); cudaGetSymbolAddress((void**)&wil, g_wil);
    cudaGetSymbolAddress((void**)&wxh, g_wxh); cudaGetSymbolAddress((void**)&wxl, g_wxl);
    cudaGetSymbolAddress((void**)&wdh, g_wdh); cudaGetSymbolAddress((void**)&wdl, g_wdl);
    cudaGetSymbolAddress((void**)&woh, g_woh); cudaGetSymbolAddress((void**)&wol, g_wol);

    cudaFuncSetAttribute(tc_gemm<0>, cudaFuncAttributeMaxDynamicSharedMemorySize, SMEMDYN);
    cudaFuncSetAttribute(tc_gemm<1>, cudaFuncAttributeMaxDynamicSharedMemorySize, SMEMDYN);
    cudaFuncSetAttribute(tc_gemm<2>, cudaFuncAttributeMaxDynamicSharedMemorySize, SMEMDYN);
    cudaFuncSetAttribute(tc_gemm<3>, cudaFuncAttributeMaxDynamicSharedMemorySize, SMEMDYN);

    // ---- splits (5 launches; launch index 5 = in_proj layer 0, profiled) ----
    split_tiled<<<dim3(cdiv(NTOK*DM, 256), 1), 256>>>(x, 0, 0, NTOK, DM, DM, x0h, x0l);
    split_tiled<<<dim3(cdiv(2*DI*DM, 256), 2), 256>>>(Wi, (size_t)2*DI*DM, (size_t)2*DI*DM,
                                                      2*DI, DM, DM, wih, wil);
    split_tiled<<<dim3(cdiv(XPD*DI, 256), 2), 256>>>(Wx, (size_t)XPD*DI, (size_t)XPDP*DI,
                                                     XPD, DI, DI, wxh, wxl);
    split_tiled<<<dim3(cdiv(DI*DTR, 256), 2), 256>>>(Wdt, (size_t)DI*DTR, (size_t)DI*DTKP,
                                                     DI, DTR, DTKP, wdh, wdl);
    split_tiled<<<dim3(cdiv(DM*DI, 256), 2), 256>>>(Wo, (size_t)DM*DI, (size_t)DM*DI,
                                                    DM, DI, DI, woh, wol);

    const bf16* curh = x0h;
    const bf16* curl = x0l;
    for (int l = 0; l < 2; l++) {
        const float* cw_l  = cw   + (size_t)l * DI * 4;
        const float* cb_l  = cb   + (size_t)l * DI;
        const float* bdt_l = bdt  + (size_t)l * DI;
        const float* Al_l  = Alog + (size_t)l * DI * DSTATE;
        const float* Dp_l  = Dp   + (size_t)l * DI;

        // in_proj: [8192 x 3072], K=768
        tc_gemm<0><<<dim3(24, 64), 256, SMEMDYN>>>(
            curh, curl, wih + (size_t)l*2*DI*DM, wil + (size_t)l*2*DI*DM,
            nullptr, p_xz, 2*DI, nullptr, nullptr, 0, DM);

        dim3 gc(SEQ / 32, DI / 32, BATCH);
        conv_silu_kernel<<<gc, dim3(32, 32)>>>(p_xz, cw_l, cb_l, xch, xcl, p_uT);

        // x_proj: [8192 x 176], K=1536; also emits tiled dt-A (cols < 48)
        tc_gemm<2><<<dim3(2, 64), 256, SMEMDYN>>>(
            xch, xcl, wxh + (size_t)l*XPDP*DI, wxl + (size_t)l*XPDP*DI,
            nullptr, p_xdbl, XPD, dah, dal, DTKP, DI);

        // dt: [8192 x 1536], K=64; softplus+bias, transposed store into dtT
        tc_gemm<1><<<dim3(12, 64), 256, SMEMDYN>>>(
            dah, dal, wdh + (size_t)l*DI*DTKP, wdl + (size_t)l*DI*DTKP,
            bdt_l, p_dtT, DI, nullptr, nullptr, 0, DTKP);

        scan_kernel<<<(BATCH * DI) / 4, 128>>>(p_dtT, p_uT, p_xdbl, Al_l, p_yT);

        gate_kernel<<<gc, dim3(32, 32)>>>(p_yT, p_uT, Dp_l, p_xz, gth, gtl);

        // out_proj: [8192 x 768], K=1536
        if (l == 0) {
            tc_gemm<3><<<dim3(6, 64), 256, SMEMDYN>>>(
                gth, gtl, woh + (size_t)l*DM*DI, wol + (size_t)l*DM*DI,
                nullptr, nullptr, DM, x1h, x1l, DM, DI);
            curh = x1h; curl = x1l;
        } else {
            tc_gemm<0><<<dim3(6, 64), 256, SMEMDYN>>>(
                gth, gtl, woh + (size_t)l*DM*DI, wol + (size_t)l*DM*DI,
                nullptr, (float*)d_out, DM, nullptr, nullptr, 0, DI);
        }
    }
}

// round 7
// speedup vs baseline: 1.0228x; 1.0228x over previous
#include <cuda_runtime.h>
#include <cuda_bf16.h>
#include <math.h>
#include <stdint.h>

#define BATCH   4
#define SEQ     2048
#define DM      768
#define DI      1536
#define DSTATE  64
#define DTR     48
#define XPD     (DTR + 2*DSTATE)   // 176
#define XPDP    256                // padded rows for x_proj weight
#define DTKP    64                 // padded K for dt GEMM (48 -> 64)
#define NTOK    (BATCH*SEQ)        // 8192

typedef __nv_bfloat16 bf16;

// ---------------- scratch (static device globals; zero-initialized) ---------
__device__ __align__(256) float g_xz   [(size_t)NTOK * 2*DI];
__device__ __align__(256) float g_uT   [(size_t)BATCH*DI*SEQ];
__device__ __align__(256) float g_xdbl [(size_t)NTOK * XPD];
__device__ __align__(256) float g_dtT  [(size_t)BATCH*DI*SEQ];
__device__ __align__(256) float g_yT   [(size_t)BATCH*DI*SEQ];

// bf16 hi/lo operand buffers in TILED layout (pads stay zero: never written)
__device__ __align__(256) bf16 g_x0h[(size_t)NTOK*DM],  g_x0l[(size_t)NTOK*DM];
__device__ __align__(256) bf16 g_x1h[(size_t)NTOK*DM],  g_x1l[(size_t)NTOK*DM];
__device__ __align__(256) bf16 g_xch[(size_t)NTOK*DI],  g_xcl[(size_t)NTOK*DI];
__device__ __align__(256) bf16 g_dah[(size_t)NTOK*DTKP],g_dal[(size_t)NTOK*DTKP];
__device__ __align__(256) bf16 g_gth[(size_t)NTOK*DI],  g_gtl[(size_t)NTOK*DI];
__device__ __align__(256) bf16 g_wih[(size_t)2*2*DI*DM], g_wil[(size_t)2*2*DI*DM];
__device__ __align__(256) bf16 g_wxh[(size_t)2*XPDP*DI], g_wxl[(size_t)2*XPDP*DI];
__device__ __align__(256) bf16 g_wdh[(size_t)2*DI*DTKP], g_wdl[(size_t)2*DI*DTKP];
__device__ __align__(256) bf16 g_woh[(size_t)2*DM*DI],   g_wol[(size_t)2*DM*DI];

// ---------------- tiled layout ----------------
// 128-row x 32-col tiles of bf16 (4096 elems = 8KB, contiguous).
// Within tile: 64B rows, four 16B granules, granule XOR-swizzled by (r>>1)&3.
__device__ __forceinline__ size_t toff(int r, int c, int K) {
    return ((size_t)((r >> 7) * (K >> 5) + (c >> 5))) * 4096
         + (size_t)((r & 127) * 32
         + (((((c >> 3) & 3) ^ ((r >> 1) & 3)) << 3) | (c & 7)));
}

// ---------------- PTX helpers ----------------
__device__ __forceinline__ void split_bf(float x, bf16& h, bf16& l) {
    h = __float2bfloat16(x);
    l = __float2bfloat16(x - __bfloat162float(h));
}

__device__ __forceinline__ void bulkcp(uint32_t dst, const void* src,
                                       uint32_t bytes, uint32_t mbar) {
    asm volatile(
        "cp.async.bulk.shared::cluster.global.mbarrier::complete_tx::bytes "
        "[%0], [%1], %2, [%3];"
        :: "r"(dst), "l"(src), "r"(bytes), "r"(mbar) : "memory");
}

#define MBAR_INIT(addr, cnt) \
    asm volatile("mbarrier.init.shared.b64 [%0], %1;" :: "r"(addr), "r"(cnt) : "memory")
#define MBAR_INVAL(addr) \
    asm volatile("mbarrier.inval.shared.b64 [%0];" :: "r"(addr) : "memory")
#define MBAR_EXPECT_TX(addr, bytes) \
    asm volatile("mbarrier.arrive.expect_tx.shared.b64 _, [%0], %1;" \
        :: "r"(addr), "r"((uint32_t)(bytes)) : "memory")
#define MBAR_ARRIVE(addr) \
    asm volatile("mbarrier.arrive.shared.b64 _, [%0];" :: "r"(addr) : "memory")

#define MBAR_WAIT(mbar_addr, phase_parity) do { \
    uint32_t _mbar = (uint32_t)(mbar_addr); \
    uint32_t _parity = (uint32_t)(phase_parity); \
    uint32_t _done; \
    asm volatile("{\n\t.reg .pred p;\n\t" \
        "mbarrier.try_wait.parity.acquire.cta.shared::cta.b64 p, [%1], %2;\n\t" \
        "selp.b32 %0, 1, 0, p;\n\t}" \
        : "=r"(_done) : "r"(_mbar), "r"(_parity) : "memory"); \
    if (!_done) { \
        asm volatile("{\n\t.reg .pred P1;\n\t" \
            "WAIT_LOOP_%=:\n\t" \
            "mbarrier.try_wait.parity.acquire.cta.shared::cta.b64 P1, [%0], %1, 0x989680;\n\t" \
            "@P1 bra.uni WAIT_DONE_%=;\n\t" \
            "bra.uni WAIT_LOOP_%=;\n\t" \
            "WAIT_DONE_%=:\n\t}" \
            :: "r"(_mbar), "r"(_parity) : "memory"); \
    } \
} while(0)

__device__ __forceinline__ void ldsm_x4(uint32_t& r0, uint32_t& r1, uint32_t& r2, uint32_t& r3, uint32_t a) {
    asm volatile("ldmatrix.sync.aligned.m8n8.x4.shared.b16 {%0,%1,%2,%3}, [%4];"
                 : "=r"(r0), "=r"(r1), "=r"(r2), "=r"(r3) : "r"(a));
}
__device__ __forceinline__ void ldsm_x2(uint32_t& r0, uint32_t& r1, uint32_t a) {
    asm volatile("ldmatrix.sync.aligned.m8n8.x2.shared.b16 {%0,%1}, [%2];"
                 : "=r"(r0), "=r"(r1) : "r"(a));
}
__device__ __forceinline__ void mma_bf16(float* d, const uint32_t* a, const uint32_t* b) {
    asm volatile(
        "mma.sync.aligned.m16n8k16.row.col.f32.bf16.bf16.f32 "
        "{%0,%1,%2,%3}, {%4,%5,%6,%7}, {%8,%9}, {%0,%1,%2,%3};"
        : "+f"(d[0]), "+f"(d[1]), "+f"(d[2]), "+f"(d[3])
        : "r"(a[0]), "r"(a[1]), "r"(a[2]), "r"(a[3]), "r"(b[0]), "r"(b[1]));
}

// ---------------- bulk-copy bf16x3 GEMM ----------------
// C[M,N] = (Ah+Al)[M,K] * (Bh+Bl)[N,K]^T, operands in tiled layout.
// CTA tile 128x128, 256 thr (8 warps 2x4), warp tile 64x32, k-chunk 32.
// 3-stage mbarrier ring, 1 cp.async.bulk per 8KB tile (4 per stage).
// 96KB SMEM -> 2 CTAs/SM (launch_bounds(256,2)) for latency hiding.
#define NST 3
#define STG 32768
#define AUXB (NST*STG)            // 98304
#define SMEMDYN (AUXB + 128)

template<int EPI>
__global__ __launch_bounds__(256, 2)
void tc_gemm(const bf16* __restrict__ Ah, const bf16* __restrict__ Al,
             const bf16* __restrict__ Bh, const bf16* __restrict__ Bl,
             const float* __restrict__ bias,
             float* __restrict__ C, int N,
             bf16* __restrict__ Ho, bf16* __restrict__ Lo, int Kho,
             int K)
{
    extern __shared__ __align__(1024) uint8_t sm[];
    const uint32_t smb = (uint32_t)__cvta_generic_to_shared(sm);
    const int tid = threadIdx.x, lane = tid & 31, wid = tid >> 5;
    const int warpM = wid >> 2, warpN = wid & 3;
    const int rowBlk = blockIdx.y * 128, colBlk = blockIdx.x * 128;
    const int fr = lane >> 2, fc = lane & 3;
    const int nk = K >> 5;

    const bf16* pAh = Ah + (size_t)blockIdx.y * nk * 4096;
    const bf16* pAl = Al + (size_t)blockIdx.y * nk * 4096;
    const bf16* pBh = Bh + (size_t)blockIdx.x * nk * 4096;
    const bf16* pBl = Bl + (size_t)blockIdx.x * nk * 4096;

    if (tid == 0) {
#pragma unroll
        for (int s = 0; s < NST; s++) {
            MBAR_INIT(smb + AUXB + s * 8, 1);        // full
            MBAR_INIT(smb + AUXB + 64 + s * 8, 8);   // empty
        }
    }
    __syncthreads();

    if (tid == 0) {
        int pre = nk < NST ? nk : NST;
        for (int s = 0; s < pre; s++) {
            uint32_t mb = smb + AUXB + s * 8;
            MBAR_EXPECT_TX(mb, 4 * 8192);
            uint32_t d = smb + s * STG;
            bulkcp(d,         pAh + (size_t)s * 4096, 8192, mb);
            bulkcp(d + 8192,  pAl + (size_t)s * 4096, 8192, mb);
            bulkcp(d + 16384, pBh + (size_t)s * 4096, 8192, mb);
            bulkcp(d + 24576, pBl + (size_t)s * 4096, 8192, mb);
        }
    }

    float acc[4][4][4];
#pragma unroll
    for (int mt = 0; mt < 4; mt++)
#pragma unroll
        for (int nt = 0; nt < 4; nt++)
#pragma unroll
            for (int q = 0; q < 4; q++) acc[mt][nt][q] = 0.f;

    uint32_t arow[4], asw[4], brow[4], bsw[4];
#pragma unroll
    for (int mt = 0; mt < 4; mt++) {
        int r = warpM * 64 + mt * 16 + (lane & 15);
        arow[mt] = r * 64; asw[mt] = (r >> 1) & 3;
    }
#pragma unroll
    for (int nt = 0; nt < 4; nt++) {
        int n = warpN * 32 + nt * 8 + (lane & 7);
        brow[nt] = n * 64; bsw[nt] = (n >> 1) & 3;
    }
    const int akg = lane >> 4;
    const int bkg = (lane >> 3) & 1;

    for (int c = 0; c < nk; c++) {
        const int st = c % NST;
        const int ph = (c / NST) & 1;
        MBAR_WAIT(smb + AUXB + st * 8, ph);

        const uint32_t sA = smb + st * STG;
        const uint32_t sB = sA + 16384;
#pragma unroll
        for (int ks = 0; ks < 2; ks++) {
            uint32_t bh[4][2], bl[4][2];
#pragma unroll
            for (int nt = 0; nt < 4; nt++) {
                uint32_t off = brow[nt] + (((ks * 2 + bkg) ^ bsw[nt]) << 4);
                ldsm_x2(bh[nt][0], bh[nt][1], sB + off);
                ldsm_x2(bl[nt][0], bl[nt][1], sB + 8192 + off);
            }
#pragma unroll
            for (int mt = 0; mt < 4; mt++) {
                uint32_t off = arow[mt] + (((ks * 2 + akg) ^ asw[mt]) << 4);
                uint32_t ah[4], al[4];
                ldsm_x4(ah[0], ah[1], ah[2], ah[3], sA + off);
                ldsm_x4(al[0], al[1], al[2], al[3], sA + 8192 + off);
#pragma unroll
                for (int nt = 0; nt < 4; nt++) {
                    mma_bf16(acc[mt][nt], ah, bh[nt]);
                    mma_bf16(acc[mt][nt], ah, bl[nt]);
                    mma_bf16(acc[mt][nt], al, bh[nt]);
                }
            }
        }
        if (lane == 0) MBAR_ARRIVE(smb + AUXB + 64 + st * 8);

        if (tid == 0 && c + NST < nk) {
            MBAR_WAIT(smb + AUXB + 64 + st * 8, ph);   // all 8 warps done with stage st
            uint32_t mb = smb + AUXB + st * 8;
            MBAR_EXPECT_TX(mb, 4 * 8192);
            uint32_t d = smb + st * STG;
            size_t o = (size_t)(c + NST) * 4096;
            bulkcp(d,         pAh + o, 8192, mb);
            bulkcp(d + 8192,  pAl + o, 8192, mb);
            bulkcp(d + 16384, pBh + o, 8192, mb);
            bulkcp(d + 24576, pBl + o, 8192, mb);
        }
    }

    // ---- epilogue ----
#pragma unroll
    for (int mt = 0; mt < 4; mt++) {
#pragma unroll
        for (int nt = 0; nt < 4; nt++) {
            int gr0 = rowBlk + warpM * 64 + mt * 16 + fr;
            int gc  = colBlk + warpN * 32 + nt * 8 + 2 * fc;
            if (EPI == 0) {
                *(float2*)&C[(size_t)gr0 * N + gc] =
                    make_float2(acc[mt][nt][0], acc[mt][nt][1]);
                *(float2*)&C[(size_t)(gr0 + 8) * N + gc] =
                    make_float2(acc[mt][nt][2], acc[mt][nt][3]);
            } else if (EPI == 1) {
                float bv0 = bias[gc], bv1 = bias[gc + 1];
#pragma unroll
                for (int h = 0; h < 2; h++) {
                    int gr = gr0 + h * 8;
                    int b = gr >> 11, t = gr & (SEQ - 1);
                    float v0 = acc[mt][nt][h * 2 + 0] + bv0;
                    float v1 = acc[mt][nt][h * 2 + 1] + bv1;
                    v0 = (v0 > 20.f) ? v0 : log1pf(__expf(v0));
                    v1 = (v1 > 20.f) ? v1 : log1pf(__expf(v1));
                    C[((size_t)b * DI + gc)     * SEQ + t] = v0;
                    C[((size_t)b * DI + gc + 1) * SEQ + t] = v1;
                }
            } else if (EPI == 2) {
#pragma unroll
                for (int h = 0; h < 2; h++) {
                    int gr = gr0 + h * 8;
                    float v0 = acc[mt][nt][h * 2 + 0];
                    float v1 = acc[mt][nt][h * 2 + 1];
                    if (gc < N) {
                        C[(size_t)gr * N + gc]     = v0;
                        C[(size_t)gr * N + gc + 1] = v1;
                    }
                    if (gc < DTR) {
                        bf16 h0, l0, h1, l1;
                        split_bf(v0, h0, l0); split_bf(v1, h1, l1);
                        size_t o = toff(gr, gc, DTKP);
                        *(uint32_t*)&Ho[o] = (uint32_t)__bfloat16_as_ushort(h0)
                                           | ((uint32_t)__bfloat16_as_ushort(h1) << 16);
                        *(uint32_t*)&Lo[o] = (uint32_t)__bfloat16_as_ushort(l0)
                                           | ((uint32_t)__bfloat16_as_ushort(l1) << 16);
                    }
                }
            } else {   // EPI 3
#pragma unroll
                for (int h = 0; h < 2; h++) {
                    int gr = gr0 + h * 8;
                    bf16 h0, l0, h1, l1;
                    split_bf(acc[mt][nt][h * 2 + 0], h0, l0);
                    split_bf(acc[mt][nt][h * 2 + 1], h1, l1);
                    size_t o = toff(gr, gc, Kho);
                    *(uint32_t*)&Ho[o] = (uint32_t)__bfloat16_as_ushort(h0)
                                       | ((uint32_t)__bfloat16_as_ushort(h1) << 16);
                    *(uint32_t*)&Lo[o] = (uint32_t)__bfloat16_as_ushort(l0)
                                       | ((uint32_t)__bfloat16_as_ushort(l1) << 16);
                }
            }
        }
    }

    __syncthreads();
    if (tid == 0) {
#pragma unroll
        for (int s = 0; s < NST; s++) {
            MBAR_INVAL(smb + AUXB + s * 8);
            MBAR_INVAL(smb + AUXB + 64 + s * 8);
        }
    }
}

// ---------------- f32 -> (hi, lo) bf16 split into tiled layout ----------------
__global__ __launch_bounds__(256)
void split_tiled(const float* __restrict__ in, size_t sstride, size_t dstride,
                 int rows, int cols, int K,
                 bf16* __restrict__ H, bf16* __restrict__ L)
{
    const float* src = in + (size_t)blockIdx.y * sstride;
    bf16* h = H + (size_t)blockIdx.y * dstride;
    bf16* l = L + (size_t)blockIdx.y * dstride;
    int i = blockIdx.x * 256 + threadIdx.x;
    if (i >= rows * cols) return;
    int r = i / cols, c = i - r * cols;
    float x = src[(size_t)r * cols + c];
    bf16 hh, ll; split_bf(x, hh, ll);
    size_t o = toff(r, c, K);
    h[o] = hh; l[o] = ll;
}

// ---------------- merged split for Wx / Wdt / Wo (per layer in blockIdx.y) ---
#define SEG0 (XPD*DI)        // 270336 = 1056*256
#define SEG1 (DI*DTR)        // 73728  = 288*256
#define SEG2 (DM*DI)         // 1179648= 4608*256
__global__ __launch_bounds__(256)
void split_rest(const float* __restrict__ Wx, const float* __restrict__ Wdt,
                const float* __restrict__ Wo,
                bf16* __restrict__ wxh, bf16* __restrict__ wxl,
                bf16* __restrict__ wdh, bf16* __restrict__ wdl,
                bf16* __restrict__ woh, bf16* __restrict__ wol)
{
    const int l = blockIdx.y;
    int i = blockIdx.x * 256 + threadIdx.x;
    float x; bf16* H; bf16* L; size_t o;
    if (i < SEG0) {
        int r = i / DI, c = i - r * DI;
        x = Wx[(size_t)l * SEG0 + i];
        H = wxh + (size_t)l * XPDP * DI; L = wxl + (size_t)l * XPDP * DI;
        o = toff(r, c, DI);
    } else if (i < SEG0 + SEG1) {
        int j = i - SEG0;
        int r = j / DTR, c = j - r * DTR;
        x = Wdt[(size_t)l * SEG1 + j];
        H = wdh + (size_t)l * DI * DTKP; L = wdl + (size_t)l * DI * DTKP;
        o = toff(r, c, DTKP);
    } else {
        int j = i - SEG0 - SEG1;
        int r = j / DI, c = j - r * DI;
        x = Wo[(size_t)l * SEG2 + j];
        H = woh + (size_t)l * DM * DI; L = wol + (size_t)l * DM * DI;
        o = toff(r, c, DI);
    }
    bf16 hh, ll; split_bf(x, hh, ll);
    H[o] = hh; L[o] = ll;
}

// ---------------- causal depthwise conv (K=4) + SiLU ----------------
__global__ __launch_bounds__(1024)
void conv_silu_kernel(const float* __restrict__ xz,
                      const float* __restrict__ cw, const float* __restrict__ cb,
                      bf16* __restrict__ xch, bf16* __restrict__ xcl,
                      float* __restrict__ uT)
{
    __shared__ float xs[35][33];
    __shared__ float ys[32][33];
    const int tx = threadIdx.x, ty = threadIdx.y;
    const int t0 = blockIdx.x * 32, d0 = blockIdx.y * 32, b = blockIdx.z;

    for (int r = ty; r < 35; r += 32) {
        int t = t0 - 3 + r;
        xs[r][tx] = (t >= 0) ? xz[((size_t)b * SEQ + t) * (2 * DI) + d0 + tx] : 0.f;
    }
    __syncthreads();

    const int d = d0 + tx;
    const float w0 = cw[d * 4 + 0], w1 = cw[d * 4 + 1],
                w2 = cw[d * 4 + 2], w3 = cw[d * 4 + 3];
    float acc = cb[d];
    acc = fmaf(w0, xs[ty + 0][tx], acc);
    acc = fmaf(w1, xs[ty + 1][tx], acc);
    acc = fmaf(w2, xs[ty + 2][tx], acc);
    acc = fmaf(w3, xs[ty + 3][tx], acc);
    float v = acc / (1.f + __expf(-acc));

    bf16 h, l; split_bf(v, h, l);
    size_t o = toff(b * SEQ + t0 + ty, d, DI);
    xch[o] = h; xcl[o] = l;
    ys[ty][tx] = v;
    __syncthreads();
    uT[((size_t)b * DI + d0 + ty) * SEQ + t0 + tx] = ys[tx][ty];
}

// ---------------- selective scan: one warp per (b, d) channel ----------------
__global__ __launch_bounds__(128)
void scan_kernel(const float* __restrict__ dtT, const float* __restrict__ uT,
                 const float* __restrict__ xdbl, const float* __restrict__ A_log,
                 float* __restrict__ yT)
{
    const int wid  = blockIdx.x * (blockDim.x >> 5) + (threadIdx.x >> 5);
    const int lane = threadIdx.x & 31;
    const int b = wid / DI;
    const int d = wid % DI;

    const float A0 = -__expf(A_log[(size_t)d * DSTATE + lane]);
    const float A1 = -__expf(A_log[(size_t)d * DSTATE + lane + 32]);
    float h0 = 0.f, h1 = 0.f;

    const float* dtp = dtT + ((size_t)b * DI + d) * SEQ;
    const float* up  = uT  + ((size_t)b * DI + d) * SEQ;
    float*       yp  = yT  + ((size_t)b * DI + d) * SEQ;

    for (int t0 = 0; t0 < SEQ; t0 += 32) {
        float dtc = dtp[t0 + lane];
        float uc  = up [t0 + lane];
        float ykeep = 0.f;
        const float* bc = xdbl + ((size_t)b * SEQ + t0) * XPD;
#pragma unroll 4
        for (int s = 0; s < 32; s++) {
            float dts = __shfl_sync(0xffffffffu, dtc, s);
            float us  = __shfl_sync(0xffffffffu, uc,  s);
            const float* row = bc + (size_t)s * XPD + DTR;
            float Bn0 = __ldg(row + lane);
            float Bn1 = __ldg(row + lane + 32);
            float Cn0 = __ldg(row + 64 + lane);
            float Cn1 = __ldg(row + 64 + lane + 32);
            float du = dts * us;
            h0 = fmaf(__expf(dts * A0), h0, du * Bn0);
            h1 = fmaf(__expf(dts * A1), h1, du * Bn1);
            float yv = fmaf(h0, Cn0, h1 * Cn1);
#pragma unroll
            for (int off = 16; off; off >>= 1)
                yv += __shfl_xor_sync(0xffffffffu, yv, off);
            if (lane == s) ykeep = yv;
        }
        yp[t0 + lane] = ykeep;
    }
}

// ---------------- gate: (y + D*u) * silu(z) -> tiled (hi, lo) bf16 ----------
__global__ __launch_bounds__(1024)
void gate_kernel(const float* __restrict__ yT, const float* __restrict__ uT,
                 const float* __restrict__ Dp, const float* __restrict__ xz,
                 bf16* __restrict__ gth, bf16* __restrict__ gtl)
{
    __shared__ float s[32][33];
    const int tx = threadIdx.x, ty = threadIdx.y;
    const int t0 = blockIdx.x * 32, d0 = blockIdx.y * 32, b = blockIdx.z;

    size_t idx = ((size_t)b * DI + d0 + ty) * SEQ + t0 + tx;
    s[ty][tx] = yT[idx] + Dp[d0 + ty] * uT[idx];
    __syncthreads();

    const int t = t0 + ty, d = d0 + tx;
    float z  = xz[((size_t)b * SEQ + t) * (2 * DI) + DI + d];
    float sz = z / (1.f + __expf(-z));
    float v  = s[tx][ty] * sz;
    bf16 h, l; split_bf(v, h, l);
    size_t o = toff(b * SEQ + t, d, DI);
    gth[o] = h; gtl[o] = l;
}

// ---------------- host ----------------
static inline int cdiv(int a, int b) { return (a + b - 1) / b; }

extern "C" void kernel_launch(void* const* d_in, const int* in_sizes, int n_in,
                              void* d_out, int out_size)
{
    const float* x    = (const float*)d_in[0];
    const float* Wi   = (const float*)d_in[1];
    const float* cw   = (const float*)d_in[2];
    const float* cb   = (const float*)d_in[3];
    const float* Wx   = (const float*)d_in[4];
    const float* Wdt  = (const float*)d_in[5];
    const float* bdt  = (const float*)d_in[6];
    const float* Alog = (const float*)d_in[7];
    const float* Dp   = (const float*)d_in[8];
    const float* Wo   = (const float*)d_in[9];

    float *p_xz, *p_uT, *p_xdbl, *p_dtT, *p_yT;
    cudaGetSymbolAddress((void**)&p_xz,   g_xz);
    cudaGetSymbolAddress((void**)&p_uT,   g_uT);
    cudaGetSymbolAddress((void**)&p_xdbl, g_xdbl);
    cudaGetSymbolAddress((void**)&p_dtT,  g_dtT);
    cudaGetSymbolAddress((void**)&p_yT,   g_yT);

    bf16 *x0h, *x0l, *x1h, *x1l, *xch, *xcl, *dah, *dal, *gth, *gtl;
    bf16 *wih, *wil, *wxh, *wxl, *wdh, *wdl, *woh, *wol;
    cudaGetSymbolAddress((void**)&x0h, g_x0h); cudaGetSymbolAddress((void**)&x0l, g_x0l);
    cudaGetSymbolAddress((void**)&x1h, g_x1h); cudaGetSymbolAddress((void**)&x1l, g_x1l);
    cudaGetSymbolAddress((void**)&xch, g_xch); cudaGetSymbolAddress((void**)&xcl, g_xcl);
    cudaGetSymbolAddress((void**)&dah, g_dah); cudaGetSymbolAddress((void**)&dal, g_dal);
    cudaGetSymbolAddress((void**)&gth, g_gth); cudaGetSymbolAddress((void**)&gtl, g_gtl);
    cudaGetSymbolAddress((void**)&wih, g_wih); cudaGetSymbolAddress((void**)&wil, g_wil);
    cudaGetSymbolAddress((void**)&wxh, g_wxh); cudaGetSymbolAddress((void**)&wxl, g_wxl);
    cudaGetSymbolAddress((void**)&wdh, g_wdh); cudaGetSymbolAddress((void**)&wdl, g_wdl);
    cudaGetSymbolAddress((void**)&woh, g_woh); cudaGetSymbolAddress((void**)&wol, g_wol);

    cudaFuncSetAttribute(tc_gemm<0>, cudaFuncAttributeMaxDynamicSharedMemorySize, SMEMDYN);
    cudaFuncSetAttribute(tc_gemm<1>, cudaFuncAttributeMaxDynamicSharedMemorySize, SMEMDYN);
    cudaFuncSetAttribute(tc_gemm<2>, cudaFuncAttributeMaxDynamicSharedMemorySize, SMEMDYN);
    cudaFuncSetAttribute(tc_gemm<3>, cudaFuncAttributeMaxDynamicSharedMemorySize, SMEMDYN);

    // ---- splits: 3 launches so in_proj (layer 0) is launch #4 ----
    split_tiled<<<dim3(cdiv(NTOK*DM, 256), 1), 256>>>(x, 0, 0, NTOK, DM, DM, x0h, x0l);
    split_tiled<<<dim3(cdiv(2*DI*DM, 256), 2), 256>>>(Wi, (size_t)2*DI*DM, (size_t)2*DI*DM,
                                                      2*DI, DM, DM, wih, wil);
    split_rest<<<dim3((SEG0 + SEG1 + SEG2) / 256, 2), 256>>>(
        Wx, Wdt, Wo, wxh, wxl, wdh, wdl, woh, wol);

    const bf16* curh = x0h;
    const bf16* curl = x0l;
    for (int l = 0; l < 2; l++) {
        const float* cw_l  = cw   + (size_t)l * DI * 4;
        const float* cb_l  = cb   + (size_t)l * DI;
        const float* bdt_l = bdt  + (size_t)l * DI;
        const float* Al_l  = Alog + (size_t)l * DI * DSTATE;
        const float* Dp_l  = Dp   + (size_t)l * DI;

        // in_proj: [8192 x 3072], K=768  (launch #4 in layer 0 -> profiled)
        tc_gemm<0><<<dim3(24, 64), 256, SMEMDYN>>>(
            curh, curl, wih + (size_t)l*2*DI*DM, wil + (size_t)l*2*DI*DM,
            nullptr, p_xz, 2*DI, nullptr, nullptr, 0, DM);

        dim3 gc(SEQ / 32, DI / 32, BATCH);
        conv_silu_kernel<<<gc, dim3(32, 32)>>>(p_xz, cw_l, cb_l, xch, xcl, p_uT);

        // x_proj: [8192 x 176], K=1536; also emits tiled dt-A (cols < 48)
        tc_gemm<2><<<dim3(2, 64), 256, SMEMDYN>>>(
            xch, xcl, wxh + (size_t)l*XPDP*DI, wxl + (size_t)l*XPDP*DI,
            nullptr, p_xdbl, XPD, dah, dal, DTKP, DI);

        // dt: [8192 x 1536], K=64; softplus+bias, transposed store into dtT
        tc_gemm<1><<<dim3(12, 64), 256, SMEMDYN>>>(
            dah, dal, wdh + (size_t)l*DI*DTKP, wdl + (size_t)l*DI*DTKP,
            bdt_l, p_dtT, DI, nullptr, nullptr, 0, DTKP);

        scan_kernel<<<(BATCH * DI) / 4, 128>>>(p_dtT, p_uT, p_xdbl, Al_l, p_yT);

        gate_kernel<<<gc, dim3(32, 32)>>>(p_yT, p_uT, Dp_l, p_xz, gth, gtl);

        // out_proj: [8192 x 768], K=1536
        if (l == 0) {
            tc_gemm<3><<<dim3(6, 64), 256, SMEMDYN>>>(
                gth, gtl, woh + (size_t)l*DM*DI, wol + (size_t)l*DM*DI,
                nullptr, nullptr, DM, x1h, x1l, DM, DI);
            curh = x1h; curl = x1l;
        } else {
            tc_gemm<0><<<dim3(6, 64), 256, SMEMDYN>>>(
                gth, gtl, woh + (size_t)l*DM*DI, wol + (size_t)l*DM*DI,
                nullptr, (float*)d_out, DM, nullptr, nullptr, 0, DI);
        }
    }
}

// round 8
// speedup vs baseline: 1.2986x; 1.2696x over previous
#include <cuda_runtime.h>
#include <cuda_bf16.h>
#include <math.h>
#include <stdint.h>

#define BATCH   4
#define SEQ     2048
#define DM      768
#define DI      1536
#define DSTATE  64
#define DTR     48
#define XPD     (DTR + 2*DSTATE)   // 176
#define XPDP    256                // padded rows for x_proj weight
#define DTKP    64                 // padded K for dt GEMM (48 -> 64)
#define NTOK    (BATCH*SEQ)        // 8192

typedef __nv_bfloat16 bf16;

// ---------------- scratch (static device globals; zero-initialized) ---------
__device__ __align__(256) float g_xz   [(size_t)NTOK * 2*DI];
__device__ __align__(256) float g_uT   [(size_t)BATCH*DI*SEQ];
__device__ __align__(256) float g_xdbl [(size_t)NTOK * XPD];
__device__ __align__(256) float g_dtT  [(size_t)BATCH*DI*SEQ];
__device__ __align__(256) float g_yT   [(size_t)BATCH*DI*SEQ];

// bf16 hi/lo operand buffers, LINEAR row-major (pads stay zero: never written)
__device__ __align__(256) bf16 g_x0h[(size_t)NTOK*DM],  g_x0l[(size_t)NTOK*DM];
__device__ __align__(256) bf16 g_x1h[(size_t)NTOK*DM],  g_x1l[(size_t)NTOK*DM];
__device__ __align__(256) bf16 g_xch[(size_t)NTOK*DI],  g_xcl[(size_t)NTOK*DI];
__device__ __align__(256) bf16 g_dah[(size_t)NTOK*DTKP],g_dal[(size_t)NTOK*DTKP];
__device__ __align__(256) bf16 g_gth[(size_t)NTOK*DI],  g_gtl[(size_t)NTOK*DI];
__device__ __align__(256) bf16 g_wih[(size_t)2*2*DI*DM], g_wil[(size_t)2*2*DI*DM];
__device__ __align__(256) bf16 g_wxh[(size_t)2*XPDP*DI], g_wxl[(size_t)2*XPDP*DI];
__device__ __align__(256) bf16 g_wdh[(size_t)2*DI*DTKP], g_wdl[(size_t)2*DI*DTKP];
__device__ __align__(256) bf16 g_woh[(size_t)2*DM*DI],   g_wol[(size_t)2*DM*DI];

// ---------------- helpers ----------------
__device__ __forceinline__ void split_bf(float x, bf16& h, bf16& l) {
    h = __float2bfloat16(x);
    l = __float2bfloat16(x - __bfloat162float(h));
}

__device__ __forceinline__ void cpasync16(uint32_t dst, const void* src) {
    asm volatile("cp.async.cg.shared.global [%0], [%1], 16;" :: "r"(dst), "l"(src));
}

__device__ __forceinline__ void ldsm_x4(uint32_t& r0, uint32_t& r1, uint32_t& r2, uint32_t& r3, uint32_t a) {
    asm volatile("ldmatrix.sync.aligned.m8n8.x4.shared.b16 {%0,%1,%2,%3}, [%4];"
                 : "=r"(r0), "=r"(r1), "=r"(r2), "=r"(r3) : "r"(a));
}
__device__ __forceinline__ void ldsm_x2(uint32_t& r0, uint32_t& r1, uint32_t a) {
    asm volatile("ldmatrix.sync.aligned.m8n8.x2.shared.b16 {%0,%1}, [%2];"
                 : "=r"(r0), "=r"(r1) : "r"(a));
}
__device__ __forceinline__ void mma_bf16(float* d, const uint32_t* a, const uint32_t* b) {
    asm volatile(
        "mma.sync.aligned.m16n8k16.row.col.f32.bf16.bf16.f32 "
        "{%0,%1,%2,%3}, {%4,%5,%6,%7}, {%8,%9}, {%0,%1,%2,%3};"
        : "+f"(d[0]), "+f"(d[1]), "+f"(d[2]), "+f"(d[3])
        : "r"(a[0]), "r"(a[1]), "r"(a[2]), "r"(a[3]), "r"(b[0]), "r"(b[1]));
}

// ---------------- bf16x3 GEMM (round-4 proven core) ----------------
// C[M,N] = (Ah+Al)[M,K](lda) * (Bh+Bl)[N,K]^T.
// Block 128x128x32, 256 thr (8 warps 2x4), warp 64x32, cp.async double-buffer.
// Tile in smem: [128 rows][32 k bf16 = 64B], 16B-group swizzle.
// EPI 0: C f32.
// EPI 1: dt-transposed: rows are CHANNELS, cols are TOKENS.
//        softplus(acc + bias[row]) -> C[(b*DI + row)*SEQ + t], coalesced in t.
// EPI 2: C f32 (cols < N) + (hi,lo) of cols < hcols into Ho/Lo[ldh].
// EPI 3: (hi,lo) only into Ho/Lo[ldh].
#define TILEB 8192
#define STAGEB (4*TILEB)

template<int EPI>
__global__ __launch_bounds__(256, 2)
void gemm_bf16x3(const bf16* __restrict__ Ah, const bf16* __restrict__ Al, int lda,
                 const bf16* __restrict__ Bh, const bf16* __restrict__ Bl,
                 const float* __restrict__ bias,
                 float* __restrict__ C, int N,
                 bf16* __restrict__ Ho, bf16* __restrict__ Lo, int ldh, int hcols,
                 int K)
{
    extern __shared__ __align__(16) uint8_t smem[];
    const uint32_t smbase = (uint32_t)__cvta_generic_to_shared(smem);

    const int tid  = threadIdx.x;
    const int lane = tid & 31;
    const int wid  = tid >> 5;
    const int warpM = wid >> 2;
    const int warpN = wid & 3;
    const int rowBlk = blockIdx.y * 128;
    const int colBlk = blockIdx.x * 128;
    const int fr = lane >> 2, fc = lane & 3;

    float acc[4][4][4];
#pragma unroll
    for (int mt = 0; mt < 4; mt++)
#pragma unroll
        for (int nt = 0; nt < 4; nt++)
#pragma unroll
            for (int q = 0; q < 4; q++) acc[mt][nt][q] = 0.f;

    const int lrow = tid >> 1;
    const int kg0  = (tid & 1) * 2;
    const int swz  = (lrow >> 1) & 3;
    const uint32_t dst0 = lrow * 64 + ((kg0 ^ swz) << 4);
    const uint32_t dst1 = lrow * 64 + (((kg0 + 1) ^ swz) << 4);
    const bf16* gAh = Ah + (size_t)(rowBlk + lrow) * lda + kg0 * 8;
    const bf16* gAl = Al + (size_t)(rowBlk + lrow) * lda + kg0 * 8;
    const bf16* gBh = Bh + (size_t)(colBlk + lrow) * K + kg0 * 8;
    const bf16* gBl = Bl + (size_t)(colBlk + lrow) * K + kg0 * 8;

    uint32_t arow[4], asw[4], brow[4], bsw[4];
#pragma unroll
    for (int mt = 0; mt < 4; mt++) {
        int r = warpM * 64 + mt * 16 + (lane & 15);
        arow[mt] = r * 64; asw[mt] = (r >> 1) & 3;
    }
#pragma unroll
    for (int nt = 0; nt < 4; nt++) {
        int n = warpN * 32 + nt * 8 + (lane & 7);
        brow[nt] = n * 64; bsw[nt] = (n >> 1) & 3;
    }
    const int akg = lane >> 4;
    const int bkg = (lane >> 3) & 1;

    const int nk = K >> 5;

    {
        uint32_t s = smbase;
        cpasync16(s + dst0,             gAh);
        cpasync16(s + dst1,             gAh + 8);
        cpasync16(s + TILEB   + dst0,   gAl);
        cpasync16(s + TILEB   + dst1,   gAl + 8);
        cpasync16(s + 2*TILEB + dst0,   gBh);
        cpasync16(s + 2*TILEB + dst1,   gBh + 8);
        cpasync16(s + 3*TILEB + dst0,   gBl);
        cpasync16(s + 3*TILEB + dst1,   gBl + 8);
        asm volatile("cp.async.commit_group;");
    }

    for (int it = 0; it < nk; it++) {
        if (it + 1 < nk) {
            uint32_t s = smbase + ((it + 1) & 1) * STAGEB;
            int ko = (it + 1) * 32;
            cpasync16(s + dst0,             gAh + ko);
            cpasync16(s + dst1,             gAh + ko + 8);
            cpasync16(s + TILEB   + dst0,   gAl + ko);
            cpasync16(s + TILEB   + dst1,   gAl + ko + 8);
            cpasync16(s + 2*TILEB + dst0,   gBh + ko);
            cpasync16(s + 2*TILEB + dst1,   gBh + ko + 8);
            cpasync16(s + 3*TILEB + dst0,   gBl + ko);
            cpasync16(s + 3*TILEB + dst1,   gBl + ko + 8);
        }
        asm volatile("cp.async.commit_group;");
        asm volatile("cp.async.wait_group 1;");
        __syncthreads();

        const uint32_t sA = smbase + (it & 1) * STAGEB;
        const uint32_t sB = sA + 2*TILEB;
#pragma unroll
        for (int ks = 0; ks < 2; ks++) {
            uint32_t bh[4][2], bl[4][2];
#pragma unroll
            for (int nt = 0; nt < 4; nt++) {
                uint32_t off = brow[nt] + (((ks * 2 + bkg) ^ bsw[nt]) << 4);
                ldsm_x2(bh[nt][0], bh[nt][1], sB + off);
                ldsm_x2(bl[nt][0], bl[nt][1], sB + TILEB + off);
            }
#pragma unroll
            for (int mt = 0; mt < 4; mt++) {
                uint32_t off = arow[mt] + (((ks * 2 + akg) ^ asw[mt]) << 4);
                uint32_t ah[4], al[4];
                ldsm_x4(ah[0], ah[1], ah[2], ah[3], sA + off);
                ldsm_x4(al[0], al[1], al[2], al[3], sA + TILEB + off);
#pragma unroll
                for (int nt = 0; nt < 4; nt++) {
                    mma_bf16(acc[mt][nt], ah, bh[nt]);
                    mma_bf16(acc[mt][nt], ah, bl[nt]);
                    mma_bf16(acc[mt][nt], al, bh[nt]);
                }
            }
        }
        __syncthreads();
    }

    // ---- epilogue ----
#pragma unroll
    for (int mt = 0; mt < 4; mt++) {
#pragma unroll
        for (int nt = 0; nt < 4; nt++) {
            int gr0 = rowBlk + warpM * 64 + mt * 16 + fr;
            int gc  = colBlk + warpN * 32 + nt * 8 + 2 * fc;
            if (EPI == 0) {
                *(float2*)&C[(size_t)gr0 * N + gc] =
                    make_float2(acc[mt][nt][0], acc[mt][nt][1]);
                *(float2*)&C[(size_t)(gr0 + 8) * N + gc] =
                    make_float2(acc[mt][nt][2], acc[mt][nt][3]);
            } else if (EPI == 1) {
                // rows = channels, cols = tokens; coalesced float2 along t
                int b = gc >> 11, t = gc & (SEQ - 1);
#pragma unroll
                for (int h = 0; h < 2; h++) {
                    int gr = gr0 + h * 8;
                    float bv = bias[gr];
                    float v0 = acc[mt][nt][h * 2 + 0] + bv;
                    float v1 = acc[mt][nt][h * 2 + 1] + bv;
                    v0 = (v0 > 20.f) ? v0 : log1pf(__expf(v0));
                    v1 = (v1 > 20.f) ? v1 : log1pf(__expf(v1));
                    *(float2*)&C[((size_t)b * DI + gr) * SEQ + t] =
                        make_float2(v0, v1);
                }
            } else if (EPI == 2) {
#pragma unroll
                for (int h = 0; h < 2; h++) {
                    int gr = gr0 + h * 8;
                    float v0 = acc[mt][nt][h * 2 + 0];
                    float v1 = acc[mt][nt][h * 2 + 1];
                    if (gc < N) {
                        C[(size_t)gr * N + gc]     = v0;
                        C[(size_t)gr * N + gc + 1] = v1;
                    }
                    if (gc < hcols) {
                        bf16 h0, l0, h1, l1;
                        split_bf(v0, h0, l0); split_bf(v1, h1, l1);
                        Ho[(size_t)gr * ldh + gc]     = h0;
                        Lo[(size_t)gr * ldh + gc]     = l0;
                        Ho[(size_t)gr * ldh + gc + 1] = h1;
                        Lo[(size_t)gr * ldh + gc + 1] = l1;
                    }
                }
            } else {   // EPI 3
#pragma unroll
                for (int h = 0; h < 2; h++) {
                    int gr = gr0 + h * 8;
                    bf16 h0, l0, h1, l1;
                    split_bf(acc[mt][nt][h * 2 + 0], h0, l0);
                    split_bf(acc[mt][nt][h * 2 + 1], h1, l1);
                    Ho[(size_t)gr * ldh + gc]     = h0;
                    Lo[(size_t)gr * ldh + gc]     = l0;
                    Ho[(size_t)gr * ldh + gc + 1] = h1;
                    Lo[(size_t)gr * ldh + gc + 1] = l1;
                }
            }
        }
    }
}

// ---------------- f32 -> (hi, lo) bf16 split, linear layout ----------------
__global__ __launch_bounds__(256)
void split_lin(const float* __restrict__ in, size_t sstr, int rows, int cols,
               bf16* __restrict__ H, bf16* __restrict__ L, size_t dstr, int out_ld)
{
    const float* src = in + (size_t)blockIdx.y * sstr;
    bf16* h = H + (size_t)blockIdx.y * dstr;
    bf16* l = L + (size_t)blockIdx.y * dstr;
    int i = blockIdx.x * 256 + threadIdx.x;
    if (i >= rows * cols) return;
    int r = i / cols, c = i - r * cols;
    bf16 hh, ll; split_bf(src[i], hh, ll);
    h[(size_t)r * out_ld + c] = hh;
    l[(size_t)r * out_ld + c] = ll;
}

// merged split for Wx / Wdt / Wo (layer = blockIdx.y)
#define SEG0 (XPD*DI)
#define SEG1 (DI*DTR)
#define SEG2 (DM*DI)
__global__ __launch_bounds__(256)
void split_rest(const float* __restrict__ Wx, const float* __restrict__ Wdt,
                const float* __restrict__ Wo,
                bf16* __restrict__ wxh, bf16* __restrict__ wxl,
                bf16* __restrict__ wdh, bf16* __restrict__ wdl,
                bf16* __restrict__ woh, bf16* __restrict__ wol)
{
    const int l = blockIdx.y;
    int i = blockIdx.x * 256 + threadIdx.x;
    float x; bf16* H; bf16* L; size_t o;
    if (i < SEG0) {
        x = Wx[(size_t)l * SEG0 + i];
        H = wxh + (size_t)l * XPDP * DI; L = wxl + (size_t)l * XPDP * DI;
        o = (size_t)i;                                   // row-major XPD x DI
    } else if (i < SEG0 + SEG1) {
        int j = i - SEG0;
        int r = j / DTR, c = j - r * DTR;
        x = Wdt[(size_t)l * SEG1 + j];
        H = wdh + (size_t)l * DI * DTKP; L = wdl + (size_t)l * DI * DTKP;
        o = (size_t)r * DTKP + c;
    } else {
        int j = i - SEG0 - SEG1;
        x = Wo[(size_t)l * SEG2 + j];
        H = woh + (size_t)l * DM * DI; L = wol + (size_t)l * DM * DI;
        o = (size_t)j;
    }
    bf16 hh, ll; split_bf(x, hh, ll);
    H[o] = hh; L[o] = ll;
}

// ---------------- causal depthwise conv (K=4) + SiLU ----------------
__global__ __launch_bounds__(1024)
void conv_silu_kernel(const float* __restrict__ xz,
                      const float* __restrict__ cw, const float* __restrict__ cb,
                      bf16* __restrict__ xch, bf16* __restrict__ xcl,
                      float* __restrict__ uT)
{
    __shared__ float xs[35][33];
    __shared__ float ys[32][33];
    const int tx = threadIdx.x, ty = threadIdx.y;
    const int t0 = blockIdx.x * 32, d0 = blockIdx.y * 32, b = blockIdx.z;

    for (int r = ty; r < 35; r += 32) {
        int t = t0 - 3 + r;
        xs[r][tx] = (t >= 0) ? xz[((size_t)b * SEQ + t) * (2 * DI) + d0 + tx] : 0.f;
    }
    __syncthreads();

    const int d = d0 + tx;
    const float w0 = cw[d * 4 + 0], w1 = cw[d * 4 + 1],
                w2 = cw[d * 4 + 2], w3 = cw[d * 4 + 3];
    float acc = cb[d];
    acc = fmaf(w0, xs[ty + 0][tx], acc);
    acc = fmaf(w1, xs[ty + 1][tx], acc);
    acc = fmaf(w2, xs[ty + 2][tx], acc);
    acc = fmaf(w3, xs[ty + 3][tx], acc);
    float v = acc / (1.f + __expf(-acc));

    bf16 h, l; split_bf(v, h, l);
    size_t oi = ((size_t)b * SEQ + t0 + ty) * DI + d;
    xch[oi] = h; xcl[oi] = l;
    ys[ty][tx] = v;
    __syncthreads();
    uT[((size_t)b * DI + d0 + ty) * SEQ + t0 + tx] = ys[tx][ty];
}

// ---------------- selective scan: one warp per (b, d) channel ----------------
// lane owns states (2*lane, 2*lane+1): B/C become float2 loads.
// y reduction via smem transpose instead of per-step butterfly.
__global__ __launch_bounds__(128)
void scan_kernel(const float* __restrict__ dtT, const float* __restrict__ uT,
                 const float* __restrict__ xdbl, const float* __restrict__ A_log,
                 float* __restrict__ yT)
{
    __shared__ float ybuf[4][32][33];
    const int w    = threadIdx.x >> 5;
    const int lane = threadIdx.x & 31;
    const int wid  = blockIdx.x * 4 + w;
    const int b = wid / DI;
    const int d = wid % DI;

    float2 Av = *(const float2*)&A_log[(size_t)d * DSTATE + 2 * lane];
    const float A0 = -__expf(Av.x);
    const float A1 = -__expf(Av.y);
    float h0 = 0.f, h1 = 0.f;

    const float* dtp = dtT + ((size_t)b * DI + d) * SEQ;
    const float* up  = uT  + ((size_t)b * DI + d) * SEQ;
    float*       yp  = yT  + ((size_t)b * DI + d) * SEQ;
    float (*yb)[33] = ybuf[w];

    for (int t0 = 0; t0 < SEQ; t0 += 32) {
        float dtc = dtp[t0 + lane];
        float uc  = up [t0 + lane];
        const float* bc = xdbl + ((size_t)b * SEQ + t0) * XPD + DTR + 2 * lane;
#pragma unroll 8
        for (int s = 0; s < 32; s++) {
            float dts = __shfl_sync(0xffffffffu, dtc, s);
            float us  = __shfl_sync(0xffffffffu, uc,  s);
            float2 Bv = *(const float2*)(bc + (size_t)s * XPD);
            float2 Cv = *(const float2*)(bc + (size_t)s * XPD + 64);
            float du = dts * us;
            h0 = fmaf(__expf(dts * A0), h0, du * Bv.x);
            h1 = fmaf(__expf(dts * A1), h1, du * Bv.y);
            yb[lane][s] = fmaf(h0, Cv.x, h1 * Cv.y);
        }
        __syncwarp();
        float acc = 0.f;
#pragma unroll
        for (int j = 0; j < 32; j++) acc += yb[j][lane];
        __syncwarp();
        yp[t0 + lane] = acc;
    }
}

// ---------------- gate: (y + D*u) * silu(z) -> (hi, lo) bf16 [t, d] ---------
__global__ __launch_bounds__(1024)
void gate_kernel(const float* __restrict__ yT, const float* __restrict__ uT,
                 const float* __restrict__ Dp, const float* __restrict__ xz,
                 bf16* __restrict__ gth, bf16* __restrict__ gtl)
{
    __shared__ float s[32][33];
    const int tx = threadIdx.x, ty = threadIdx.y;
    const int t0 = blockIdx.x * 32, d0 = blockIdx.y * 32, b = blockIdx.z;

    size_t idx = ((size_t)b * DI + d0 + ty) * SEQ + t0 + tx;
    s[ty][tx] = yT[idx] + Dp[d0 + ty] * uT[idx];
    __syncthreads();

    const int t = t0 + ty, d = d0 + tx;
    float z  = xz[((size_t)b * SEQ + t) * (2 * DI) + DI + d];
    float sz = z / (1.f + __expf(-z));
    float v  = s[tx][ty] * sz;
    bf16 h, l; split_bf(v, h, l);
    size_t oi = ((size_t)b * SEQ + t) * DI + d;
    gth[oi] = h; gtl[oi] = l;
}

// ---------------- host ----------------
static inline int cdiv(int a, int b) { return (a + b - 1) / b; }

extern "C" void kernel_launch(void* const* d_in, const int* in_sizes, int n_in,
                              void* d_out, int out_size)
{
    const float* x    = (const float*)d_in[0];
    const float* Wi   = (const float*)d_in[1];
    const float* cw   = (const float*)d_in[2];
    const float* cb   = (const float*)d_in[3];
    const float* Wx   = (const float*)d_in[4];
    const float* Wdt  = (const float*)d_in[5];
    const float* bdt  = (const float*)d_in[6];
    const float* Alog = (const float*)d_in[7];
    const float* Dp   = (const float*)d_in[8];
    const float* Wo   = (const float*)d_in[9];

    float *p_xz, *p_uT, *p_xdbl, *p_dtT, *p_yT;
    cudaGetSymbolAddress((void**)&p_xz,   g_xz);
    cudaGetSymbolAddress((void**)&p_uT,   g_uT);
    cudaGetSymbolAddress((void**)&p_xdbl, g_xdbl);
    cudaGetSymbolAddress((void**)&p_dtT,  g_dtT);
    cudaGetSymbolAddress((void**)&p_yT,   g_yT);

    bf16 *x0h, *x0l, *x1h, *x1l, *xch, *xcl, *dah, *dal, *gth, *gtl;
    bf16 *wih, *wil, *wxh, *wxl, *wdh, *wdl, *woh, *wol;
    cudaGetSymbolAddress((void**)&x0h, g_x0h); cudaGetSymbolAddress((void**)&x0l, g_x0l);
    cudaGetSymbolAddress((void**)&x1h, g_x1h); cudaGetSymbolAddress((void**)&x1l, g_x1l);
    cudaGetSymbolAddress((void**)&xch, g_xch); cudaGetSymbolAddress((void**)&xcl, g_xcl);
    cudaGetSymbolAddress((void**)&dah, g_dah); cudaGetSymbolAddress((void**)&dal, g_dal);
    cudaGetSymbolAddress((void**)&gth, g_gth); cudaGetSymbolAddress((void**)&gtl, g_gtl);
    cudaGetSymbolAddress((void**)&wih, g_wih); cudaGetSymbolAddress((void**)&wil, g_wil);
    cudaGetSymbolAddress((void**)&wxh, g_wxh); cudaGetSymbolAddress((void**)&wxl, g_wxl);
    cudaGetSymbolAddress((void**)&wdh, g_wdh); cudaGetSymbolAddress((void**)&wdl, g_wdl);
    cudaGetSymbolAddress((void**)&woh, g_woh); cudaGetSymbolAddress((void**)&wol, g_wol);

    cudaFuncSetAttribute(gemm_bf16x3<0>, cudaFuncAttributeMaxDynamicSharedMemorySize, 2*STAGEB);
    cudaFuncSetAttribute(gemm_bf16x3<1>, cudaFuncAttributeMaxDynamicSharedMemorySize, 2*STAGEB);
    cudaFuncSetAttribute(gemm_bf16x3<2>, cudaFuncAttributeMaxDynamicSharedMemorySize, 2*STAGEB);
    cudaFuncSetAttribute(gemm_bf16x3<3>, cudaFuncAttributeMaxDynamicSharedMemorySize, 2*STAGEB);

    // ---- splits (3 launches; launch idx 3 = in_proj layer 0 -> profiled) ----
    split_lin<<<dim3(cdiv(NTOK*DM, 256), 1), 256>>>(x, 0, NTOK, DM, x0h, x0l, 0, DM);
    split_lin<<<dim3(cdiv(2*DI*DM, 256), 2), 256>>>(Wi, (size_t)2*DI*DM, 2*DI, DM,
                                                    wih, wil, (size_t)2*DI*DM, DM);
    split_rest<<<dim3((SEG0 + SEG1 + SEG2) / 256, 2), 256>>>(
        Wx, Wdt, Wo, wxh, wxl, wdh, wdl, woh, wol);

    const bf16* curh = x0h;
    const bf16* curl = x0l;
    for (int l = 0; l < 2; l++) {
        const float* cw_l  = cw   + (size_t)l * DI * 4;
        const float* cb_l  = cb   + (size_t)l * DI;
        const float* bdt_l = bdt  + (size_t)l * DI;
        const float* Al_l  = Alog + (size_t)l * DI * DSTATE;
        const float* Dp_l  = Dp   + (size_t)l * DI;

        dim3 blk(256);
        // in_proj: [8192 x 3072], K=768
        gemm_bf16x3<0><<<dim3(24, 64), blk, 2*STAGEB>>>(
            curh, curl, DM, wih + (size_t)l*2*DI*DM, wil + (size_t)l*2*DI*DM,
            nullptr, p_xz, 2*DI, nullptr, nullptr, 0, 0, DM);

        dim3 gc(SEQ / 32, DI / 32, BATCH);
        conv_silu_kernel<<<gc, dim3(32, 32)>>>(p_xz, cw_l, cb_l, xch, xcl, p_uT);

        // x_proj: [8192 x 176], K=1536; also emits (hi,lo) of cols<48 into dtA
        gemm_bf16x3<2><<<dim3(2, 64), blk, 2*STAGEB>>>(
            xch, xcl, DI, wxh + (size_t)l*XPDP*DI, wxl + (size_t)l*XPDP*DI,
            nullptr, p_xdbl, XPD, dah, dal, DTKP, DTR, DI);

        // dt TRANSPOSED: C^T[1536 x 8192] = Wdt[1536,64] * dtA[8192,64]^T
        // softplus + bias[row], coalesced stores into dtT
        gemm_bf16x3<1><<<dim3(64, 12), blk, 2*STAGEB>>>(
            wdh + (size_t)l*DI*DTKP, wdl + (size_t)l*DI*DTKP, DTKP,
            dah, dal, bdt_l, p_dtT, NTOK, nullptr, nullptr, 0, 0, DTKP);

        scan_kernel<<<(BATCH * DI) / 4, 128>>>(p_dtT, p_uT, p_xdbl, Al_l, p_yT);

        gate_kernel<<<gc, dim3(32, 32)>>>(p_yT, p_uT, Dp_l, p_xz, gth, gtl);

        // out_proj: [8192 x 768], K=1536
        if (l == 0) {
            gemm_bf16x3<3><<<dim3(6, 64), blk, 2*STAGEB>>>(
                gth, gtl, DI, woh + (size_t)l*DM*DI, wol + (size_t)l*DM*DI,
                nullptr, nullptr, DM, x1h, x1l, DM, DM, DI);
            curh = x1h; curl = x1l;
        } else {
            gemm_bf16x3<0><<<dim3(6, 64), blk, 2*STAGEB>>>(
                gth, gtl, DI, woh + (size_t)l*DM*DI, wol + (size_t)l*DM*DI,
                nullptr, (float*)d_out, DM, nullptr, nullptr, 0, 0, DI);
        }
    }
}

// round 10
// speedup vs baseline: 1.6817x; 1.2951x over previous
#include <cuda_runtime.h>
#include <cuda_bf16.h>
#include <math.h>
#include <stdint.h>

#define BATCH   4
#define SEQ     2048
#define DM      768
#define DI      1536
#define DSTATE  64
#define DTR     48
#define XPD     (DTR + 2*DSTATE)   // 176
#define XPDP    256                // padded rows for x_proj weight
#define DTKP    64                 // padded K for dt GEMM (48 -> 64)
#define NTOK    (BATCH*SEQ)        // 8192

typedef __nv_bfloat16 bf16;

// ---------------- scratch (static device globals; zero-initialized) ---------
__device__ __align__(256) float g_xz   [(size_t)NTOK * 2*DI];
__device__ __align__(256) float g_uT   [(size_t)BATCH*DI*SEQ];
__device__ __align__(256) float g_xdbl [(size_t)NTOK * XPD];
__device__ __align__(256) float g_dtT  [(size_t)BATCH*DI*SEQ];
__device__ __align__(256) float g_yT   [(size_t)BATCH*DI*SEQ];

// bf16 hi/lo operand buffers, LINEAR row-major (pads stay zero: never written)
__device__ __align__(256) bf16 g_x0h[(size_t)NTOK*DM],  g_x0l[(size_t)NTOK*DM];
__device__ __align__(256) bf16 g_x1h[(size_t)NTOK*DM],  g_x1l[(size_t)NTOK*DM];
__device__ __align__(256) bf16 g_xch[(size_t)NTOK*DI],  g_xcl[(size_t)NTOK*DI];
__device__ __align__(256) bf16 g_dah[(size_t)NTOK*DTKP],g_dal[(size_t)NTOK*DTKP];
__device__ __align__(256) bf16 g_gth[(size_t)NTOK*DI],  g_gtl[(size_t)NTOK*DI];
__device__ __align__(256) bf16 g_wih[(size_t)2*2*DI*DM], g_wil[(size_t)2*2*DI*DM];
__device__ __align__(256) bf16 g_wxh[(size_t)2*XPDP*DI], g_wxl[(size_t)2*XPDP*DI];
__device__ __align__(256) bf16 g_wdh[(size_t)2*DI*DTKP], g_wdl[(size_t)2*DI*DTKP];
__device__ __align__(256) bf16 g_woh[(size_t)2*DM*DI],   g_wol[(size_t)2*DM*DI];

// ---------------- helpers ----------------
__device__ __forceinline__ void split_bf(float x, bf16& h, bf16& l) {
    h = __float2bfloat16(x);
    l = __float2bfloat16(x - __bfloat162float(h));
}

__device__ __forceinline__ void cpasync16(uint32_t dst, const void* src) {
    asm volatile("cp.async.cg.shared.global [%0], [%1], 16;" :: "r"(dst), "l"(src));
}

__device__ __forceinline__ void ldsm_x4(uint32_t& r0, uint32_t& r1, uint32_t& r2, uint32_t& r3, uint32_t a) {
    asm volatile("ldmatrix.sync.aligned.m8n8.x4.shared.b16 {%0,%1,%2,%3}, [%4];"
                 : "=r"(r0), "=r"(r1), "=r"(r2), "=r"(r3) : "r"(a));
}
__device__ __forceinline__ void ldsm_x2(uint32_t& r0, uint32_t& r1, uint32_t a) {
    asm volatile("ldmatrix.sync.aligned.m8n8.x2.shared.b16 {%0,%1}, [%2];"
                 : "=r"(r0), "=r"(r1) : "r"(a));
}
__device__ __forceinline__ void mma_bf16(float* d, const uint32_t* a, const uint32_t* b) {
    asm volatile(
        "mma.sync.aligned.m16n8k16.row.col.f32.bf16.bf16.f32 "
        "{%0,%1,%2,%3}, {%4,%5,%6,%7}, {%8,%9}, {%0,%1,%2,%3};"
        : "+f"(d[0]), "+f"(d[1]), "+f"(d[2]), "+f"(d[3])
        : "r"(a[0]), "r"(a[1]), "r"(a[2]), "r"(a[3]), "r"(b[0]), "r"(b[1]));
}

// ---------------- bf16x3 GEMM (round-4 proven core) ----------------
#define TILEB 8192
#define STAGEB (4*TILEB)

template<int EPI>
__global__ __launch_bounds__(256, 2)
void gemm_bf16x3(const bf16* __restrict__ Ah, const bf16* __restrict__ Al, int lda,
                 const bf16* __restrict__ Bh, const bf16* __restrict__ Bl,
                 const float* __restrict__ bias,
                 float* __restrict__ C, int N,
                 bf16* __restrict__ Ho, bf16* __restrict__ Lo, int ldh, int hcols,
                 int K)
{
    extern __shared__ __align__(16) uint8_t smem[];
    const uint32_t smbase = (uint32_t)__cvta_generic_to_shared(smem);

    const int tid  = threadIdx.x;
    const int lane = tid & 31;
    const int wid  = tid >> 5;
    const int warpM = wid >> 2;
    const int warpN = wid & 3;
    const int rowBlk = blockIdx.y * 128;
    const int colBlk = blockIdx.x * 128;
    const int fr = lane >> 2, fc = lane & 3;

    float acc[4][4][4];
#pragma unroll
    for (int mt = 0; mt < 4; mt++)
#pragma unroll
        for (int nt = 0; nt < 4; nt++)
#pragma unroll
            for (int q = 0; q < 4; q++) acc[mt][nt][q] = 0.f;

    const int lrow = tid >> 1;
    const int kg0  = (tid & 1) * 2;
    const int swz  = (lrow >> 1) & 3;
    const uint32_t dst0 = lrow * 64 + ((kg0 ^ swz) << 4);
    const uint32_t dst1 = lrow * 64 + (((kg0 + 1) ^ swz) << 4);
    const bf16* gAh = Ah + (size_t)(rowBlk + lrow) * lda + kg0 * 8;
    const bf16* gAl = Al + (size_t)(rowBlk + lrow) * lda + kg0 * 8;
    const bf16* gBh = Bh + (size_t)(colBlk + lrow) * K + kg0 * 8;
    const bf16* gBl = Bl + (size_t)(colBlk + lrow) * K + kg0 * 8;

    uint32_t arow[4], asw[4], brow[4], bsw[4];
#pragma unroll
    for (int mt = 0; mt < 4; mt++) {
        int r = warpM * 64 + mt * 16 + (lane & 15);
        arow[mt] = r * 64; asw[mt] = (r >> 1) & 3;
    }
#pragma unroll
    for (int nt = 0; nt < 4; nt++) {
        int n = warpN * 32 + nt * 8 + (lane & 7);
        brow[nt] = n * 64; bsw[nt] = (n >> 1) & 3;
    }
    const int akg = lane >> 4;
    const int bkg = (lane >> 3) & 1;

    const int nk = K >> 5;

    {
        uint32_t s = smbase;
        cpasync16(s + dst0,             gAh);
        cpasync16(s + dst1,             gAh + 8);
        cpasync16(s + TILEB   + dst0,   gAl);
        cpasync16(s + TILEB   + dst1,   gAl + 8);
        cpasync16(s + 2*TILEB + dst0,   gBh);
        cpasync16(s + 2*TILEB + dst1,   gBh + 8);
        cpasync16(s + 3*TILEB + dst0,   gBl);
        cpasync16(s + 3*TILEB + dst1,   gBl + 8);
        asm volatile("cp.async.commit_group;");
    }

    for (int it = 0; it < nk; it++) {
        if (it + 1 < nk) {
            uint32_t s = smbase + ((it + 1) & 1) * STAGEB;
            int ko = (it + 1) * 32;
            cpasync16(s + dst0,             gAh + ko);
            cpasync16(s + dst1,             gAh + ko + 8);
            cpasync16(s + TILEB   + dst0,   gAl + ko);
            cpasync16(s + TILEB   + dst1,   gAl + ko + 8);
            cpasync16(s + 2*TILEB + dst0,   gBh + ko);
            cpasync16(s + 2*TILEB + dst1,   gBh + ko + 8);
            cpasync16(s + 3*TILEB + dst0,   gBl + ko);
            cpasync16(s + 3*TILEB + dst1,   gBl + ko + 8);
        }
        asm volatile("cp.async.commit_group;");
        asm volatile("cp.async.wait_group 1;");
        __syncthreads();

        const uint32_t sA = smbase + (it & 1) * STAGEB;
        const uint32_t sB = sA + 2*TILEB;
#pragma unroll
        for (int ks = 0; ks < 2; ks++) {
            uint32_t bh[4][2], bl[4][2];
#pragma unroll
            for (int nt = 0; nt < 4; nt++) {
                uint32_t off = brow[nt] + (((ks * 2 + bkg) ^ bsw[nt]) << 4);
                ldsm_x2(bh[nt][0], bh[nt][1], sB + off);
                ldsm_x2(bl[nt][0], bl[nt][1], sB + TILEB + off);
            }
#pragma unroll
            for (int mt = 0; mt < 4; mt++) {
                uint32_t off = arow[mt] + (((ks * 2 + akg) ^ asw[mt]) << 4);
                uint32_t ah[4], al[4];
                ldsm_x4(ah[0], ah[1], ah[2], ah[3], sA + off);
                ldsm_x4(al[0], al[1], al[2], al[3], sA + TILEB + off);
#pragma unroll
                for (int nt = 0; nt < 4; nt++) {
                    mma_bf16(acc[mt][nt], ah, bh[nt]);
                    mma_bf16(acc[mt][nt], ah, bl[nt]);
                    mma_bf16(acc[mt][nt], al, bh[nt]);
                }
            }
        }
        __syncthreads();
    }

    // ---- epilogue ----
#pragma unroll
    for (int mt = 0; mt < 4; mt++) {
#pragma unroll
        for (int nt = 0; nt < 4; nt++) {
            int gr0 = rowBlk + warpM * 64 + mt * 16 + fr;
            int gc  = colBlk + warpN * 32 + nt * 8 + 2 * fc;
            if (EPI == 0) {
                *(float2*)&C[(size_t)gr0 * N + gc] =
                    make_float2(acc[mt][nt][0], acc[mt][nt][1]);
                *(float2*)&C[(size_t)(gr0 + 8) * N + gc] =
                    make_float2(acc[mt][nt][2], acc[mt][nt][3]);
            } else if (EPI == 1) {
                int b = gc >> 11, t = gc & (SEQ - 1);
#pragma unroll
                for (int h = 0; h < 2; h++) {
                    int gr = gr0 + h * 8;
                    float bv = bias[gr];
                    float v0 = acc[mt][nt][h * 2 + 0] + bv;
                    float v1 = acc[mt][nt][h * 2 + 1] + bv;
                    v0 = (v0 > 20.f) ? v0 : log1pf(__expf(v0));
                    v1 = (v1 > 20.f) ? v1 : log1pf(__expf(v1));
                    *(float2*)&C[((size_t)b * DI + gr) * SEQ + t] =
                        make_float2(v0, v1);
                }
            } else if (EPI == 2) {
#pragma unroll
                for (int h = 0; h < 2; h++) {
                    int gr = gr0 + h * 8;
                    float v0 = acc[mt][nt][h * 2 + 0];
                    float v1 = acc[mt][nt][h * 2 + 1];
                    if (gc < N) {
                        C[(size_t)gr * N + gc]     = v0;
                        C[(size_t)gr * N + gc + 1] = v1;
                    }
                    if (gc < hcols) {
                        bf16 h0, l0, h1, l1;
                        split_bf(v0, h0, l0); split_bf(v1, h1, l1);
                        Ho[(size_t)gr * ldh + gc]     = h0;
                        Lo[(size_t)gr * ldh + gc]     = l0;
                        Ho[(size_t)gr * ldh + gc + 1] = h1;
                        Lo[(size_t)gr * ldh + gc + 1] = l1;
                    }
                }
            } else {   // EPI 3
#pragma unroll
                for (int h = 0; h < 2; h++) {
                    int gr = gr0 + h * 8;
                    bf16 h0, l0, h1, l1;
                    split_bf(acc[mt][nt][h * 2 + 0], h0, l0);
                    split_bf(acc[mt][nt][h * 2 + 1], h1, l1);
                    Ho[(size_t)gr * ldh + gc]     = h0;
                    Lo[(size_t)gr * ldh + gc]     = l0;
                    Ho[(size_t)gr * ldh + gc + 1] = h1;
                    Lo[(size_t)gr * ldh + gc + 1] = l1;
                }
            }
        }
    }
}

// ---------------- f32 -> (hi, lo) bf16 split, linear layout ----------------
__global__ __launch_bounds__(256)
void split_lin(const float* __restrict__ in, size_t sstr, int rows, int cols,
               bf16* __restrict__ H, bf16* __restrict__ L, size_t dstr, int out_ld)
{
    const float* src = in + (size_t)blockIdx.y * sstr;
    bf16* h = H + (size_t)blockIdx.y * dstr;
    bf16* l = L + (size_t)blockIdx.y * dstr;
    int i = blockIdx.x * 256 + threadIdx.x;
    if (i >= rows * cols) return;
    int r = i / cols, c = i - r * cols;
    bf16 hh, ll; split_bf(src[i], hh, ll);
    h[(size_t)r * out_ld + c] = hh;
    l[(size_t)r * out_ld + c] = ll;
}

// merged split for Wx / Wdt / Wo (layer = blockIdx.y)
#define SEG0 (XPD*DI)
#define SEG1 (DI*DTR)
#define SEG2 (DM*DI)
__global__ __launch_bounds__(256)
void split_rest(const float* __restrict__ Wx, const float* __restrict__ Wdt,
                const float* __restrict__ Wo,
                bf16* __restrict__ wxh, bf16* __restrict__ wxl,
                bf16* __restrict__ wdh, bf16* __restrict__ wdl,
                bf16* __restrict__ woh, bf16* __restrict__ wol)
{
    const int l = blockIdx.y;
    int i = blockIdx.x * 256 + threadIdx.x;
    float x; bf16* H; bf16* L; size_t o;
    if (i < SEG0) {
        x = Wx[(size_t)l * SEG0 + i];
        H = wxh + (size_t)l * XPDP * DI; L = wxl + (size_t)l * XPDP * DI;
        o = (size_t)i;
    } else if (i < SEG0 + SEG1) {
        int j = i - SEG0;
        int r = j / DTR, c = j - r * DTR;
        x = Wdt[(size_t)l * SEG1 + j];
        H = wdh + (size_t)l * DI * DTKP; L = wdl + (size_t)l * DI * DTKP;
        o = (size_t)r * DTKP + c;
    } else {
        int j = i - SEG0 - SEG1;
        x = Wo[(size_t)l * SEG2 + j];
        H = woh + (size_t)l * DM * DI; L = wol + (size_t)l * DM * DI;
        o = (size_t)j;
    }
    bf16 hh, ll; split_bf(x, hh, ll);
    H[o] = hh; L[o] = ll;
}

// ---------------- causal depthwise conv (K=4) + SiLU ----------------
__global__ __launch_bounds__(1024)
void conv_silu_kernel(const float* __restrict__ xz,
                      const float* __restrict__ cw, const float* __restrict__ cb,
                      bf16* __restrict__ xch, bf16* __restrict__ xcl,
                      float* __restrict__ uT)
{
    __shared__ float xs[35][33];
    __shared__ float ys[32][33];
    const int tx = threadIdx.x, ty = threadIdx.y;
    const int t0 = blockIdx.x * 32, d0 = blockIdx.y * 32, b = blockIdx.z;

    for (int r = ty; r < 35; r += 32) {
        int t = t0 - 3 + r;
        xs[r][tx] = (t >= 0) ? xz[((size_t)b * SEQ + t) * (2 * DI) + d0 + tx] : 0.f;
    }
    __syncthreads();

    const int d = d0 + tx;
    const float w0 = cw[d * 4 + 0], w1 = cw[d * 4 + 1],
                w2 = cw[d * 4 + 2], w3 = cw[d * 4 + 3];
    float acc = cb[d];
    acc = fmaf(w0, xs[ty + 0][tx], acc);
    acc = fmaf(w1, xs[ty + 1][tx], acc);
    acc = fmaf(w2, xs[ty + 2][tx], acc);
    acc = fmaf(w3, xs[ty + 3][tx], acc);
    float v = acc / (1.f + __expf(-acc));

    bf16 h, l; split_bf(v, h, l);
    size_t oi = ((size_t)b * SEQ + t0 + ty) * DI + d;
    xch[oi] = h; xcl[oi] = l;
    ys[ty][tx] = v;
    __syncthreads();
    uT[((size_t)b * DI + d0 + ty) * SEQ + t0 + tx] = ys[tx][ty];
}

// ---------------- selective scan: 8 channels per CTA, B/C staged in SMEM ----
// CTA = 256 threads = 8 warps; warp w handles channel d0+w of batch b.
// Per 32-step chunk: stage B/C rows (32 x 128 floats = 16KB) once via cp.async
// double-buffer; all 8 warps consume from SMEM -> 8x less L2 traffic.
#define SCW 8
#define SCHUNK (32*128)                 // floats per stage buffer
#define SC_SMEM (2*SCHUNK*4 + SCW*32*33*4)   // 32768 + 33792 = 66560 B

__global__ __launch_bounds__(256, 3)
void scan_kernel(const float* __restrict__ dtT, const float* __restrict__ uT,
                 const float* __restrict__ xdbl, const float* __restrict__ A_log,
                 float* __restrict__ yT)
{
    extern __shared__ __align__(16) float sms[];
    float* bcs = sms;                                   // [2][32][128]
    float (*ybuf)[32][33] = (float (*)[32][33])(sms + 2 * SCHUNK);
    const uint32_t smb = (uint32_t)__cvta_generic_to_shared(sms);

    const int tid = threadIdx.x, w = tid >> 5, lane = tid & 31;
    const int b = blockIdx.y;
    const int d = blockIdx.x * SCW + w;

    float2 Av = *(const float2*)&A_log[(size_t)d * DSTATE + 2 * lane];
    const float A0 = -__expf(Av.x);
    const float A1 = -__expf(Av.y);
    float h0 = 0.f, h1 = 0.f;

    const float* dtp = dtT + ((size_t)b * DI + d) * SEQ;
    const float* up  = uT  + ((size_t)b * DI + d) * SEQ;
    float*       yp  = yT  + ((size_t)b * DI + d) * SEQ;
    const float* xb  = xdbl + (size_t)b * SEQ * XPD + DTR;   // + t*XPD for row t
    float (*yb)[33] = ybuf[w];

    // stage chunk 0: 1024 16B granules, 4 per thread, coalesced
    {
#pragma unroll
        for (int q = 0; q < 4; q++) {
            int g = q * 256 + tid;
            int r = g >> 5, c = g & 31;
            cpasync16(smb + g * 16, xb + (size_t)r * XPD + c * 4);
        }
        asm volatile("cp.async.commit_group;");
    }

    for (int ch = 0; ch < SEQ / 32; ch++) {
        if (ch + 1 < SEQ / 32) {
            uint32_t dst = smb + ((ch + 1) & 1) * (SCHUNK * 4);
            int tb = (ch + 1) * 32;
#pragma unroll
            for (int q = 0; q < 4; q++) {
                int g = q * 256 + tid;
                int r = g >> 5, c = g & 31;
                cpasync16(dst + g * 16, xb + (size_t)(tb + r) * XPD + c * 4);
            }
        }
        asm volatile("cp.async.commit_group;");
        asm volatile("cp.async.wait_group 1;");
        __syncthreads();

        const int t0 = ch * 32;
        float dtc = dtp[t0 + lane];
        float uc  = up [t0 + lane];
        const float* bcp = bcs + (ch & 1) * SCHUNK;
#pragma unroll 8
        for (int s = 0; s < 32; s++) {
            float dts = __shfl_sync(0xffffffffu, dtc, s);
            float us  = __shfl_sync(0xffffffffu, uc,  s);
            float2 Bv = *(const float2*)(bcp + s * 128 + 2 * lane);
            float2 Cv = *(const float2*)(bcp + s * 128 + 64 + 2 * lane);
            float du = dts * us;
            h0 = fmaf(__expf(dts * A0), h0, du * Bv.x);
            h1 = fmaf(__expf(dts * A1), h1, du * Bv.y);
            yb[lane][s] = fmaf(h0, Cv.x, h1 * Cv.y);
        }
        __syncwarp();
        float acc = 0.f;
#pragma unroll
        for (int j = 0; j < 32; j++) acc += yb[j][lane];
        yp[t0 + lane] = acc;
        __syncthreads();   // guards stage of the buffer just consumed
    }
}

// ---------------- gate: (y + D*u) * silu(z) -> (hi, lo) bf16 [t, d] ---------
__global__ __launch_bounds__(1024)
void gate_kernel(const float* __restrict__ yT, const float* __restrict__ uT,
                 const float* __restrict__ Dp, const float* __restrict__ xz,
                 bf16* __restrict__ gth, bf16* __restrict__ gtl)
{
    __shared__ float s[32][33];
    const int tx = threadIdx.x, ty = threadIdx.y;
    const int t0 = blockIdx.x * 32, d0 = blockIdx.y * 32, b = blockIdx.z;

    size_t idx = ((size_t)b * DI + d0 + ty) * SEQ + t0 + tx;
    s[ty][tx] = yT[idx] + Dp[d0 + ty] * uT[idx];
    __syncthreads();

    const int t = t0 + ty, d = d0 + tx;
    float z  = xz[((size_t)b * SEQ + t) * (2 * DI) + DI + d];
    float sz = z / (1.f + __expf(-z));
    float v  = s[tx][ty] * sz;
    bf16 h, l; split_bf(v, h, l);
    size_t oi = ((size_t)b * SEQ + t) * DI + d;
    gth[oi] = h; gtl[oi] = l;
}

// ---------------- host ----------------
static inline int cdiv(int a, int b) { return (a + b - 1) / b; }

extern "C" void kernel_launch(void* const* d_in, const int* in_sizes, int n_in,
                              void* d_out, int out_size)
{
    const float* x    = (const float*)d_in[0];
    const float* Wi   = (const float*)d_in[1];
    const float* cw   = (const float*)d_in[2];
    const float* cb   = (const float*)d_in[3];
    const float* Wx   = (const float*)d_in[4];
    const float* Wdt  = (const float*)d_in[5];
    const float* bdt  = (const float*)d_in[6];
    const float* Alog = (const float*)d_in[7];
    const float* Dp   = (const float*)d_in[8];
    const float* Wo   = (const float*)d_in[9];

    float *p_xz, *p_uT, *p_xdbl, *p_dtT, *p_yT;
    cudaGetSymbolAddress((void**)&p_xz,   g_xz);
    cudaGetSymbolAddress((void**)&p_uT,   g_uT);
    cudaGetSymbolAddress((void**)&p_xdbl, g_xdbl);
    cudaGetSymbolAddress((void**)&p_dtT,  g_dtT);
    cudaGetSymbolAddress((void**)&p_yT,   g_yT);

    bf16 *x0h, *x0l, *x1h, *x1l, *xch, *xcl, *dah, *dal, *gth, *gtl;
    bf16 *wih, *wil, *wxh, *wxl, *wdh, *wdl, *woh, *wol;
    cudaGetSymbolAddress((void**)&x0h, g_x0h); cudaGetSymbolAddress((void**)&x0l, g_x0l);
    cudaGetSymbolAddress((void**)&x1h, g_x1h); cudaGetSymbolAddress((void**)&x1l, g_x1l);
    cudaGetSymbolAddress((void**)&xch, g_xch); cudaGetSymbolAddress((void**)&xcl, g_xcl);
    cudaGetSymbolAddress((void**)&dah, g_dah); cudaGetSymbolAddress((void**)&dal, g_dal);
    cudaGetSymbolAddress((void**)&gth, g_gth); cudaGetSymbolAddress((void**)&gtl, g_gtl);
    cudaGetSymbolAddress((void**)&wih, g_wih); cudaGetSymbolAddress((void**)&wil, g_wil);
    cudaGetSymbolAddress((void**)&wxh, g_wxh); cudaGetSymbolAddress((void**)&wxl, g_wxl);
    cudaGetSymbolAddress((void**)&wdh, g_wdh); cudaGetSymbolAddress((void**)&wdl, g_wdl);
    cudaGetSymbolAddress((void**)&woh, g_woh); cudaGetSymbolAddress((void**)&wol, g_wol);

    cudaFuncSetAttribute(gemm_bf16x3<0>, cudaFuncAttributeMaxDynamicSharedMemorySize, 2*STAGEB);
    cudaFuncSetAttribute(gemm_bf16x3<1>, cudaFuncAttributeMaxDynamicSharedMemorySize, 2*STAGEB);
    cudaFuncSetAttribute(gemm_bf16x3<2>, cudaFuncAttributeMaxDynamicSharedMemorySize, 2*STAGEB);
    cudaFuncSetAttribute(gemm_bf16x3<3>, cudaFuncAttributeMaxDynamicSharedMemorySize, 2*STAGEB);
    cudaFuncSetAttribute(scan_kernel,    cudaFuncAttributeMaxDynamicSharedMemorySize, SC_SMEM);

    // ---- splits (3 launches; launch idx 3 = in_proj layer 0 -> profiled) ----
    split_lin<<<dim3(cdiv(NTOK*DM, 256), 1), 256>>>(x, 0, NTOK, DM, x0h, x0l, 0, DM);
    split_lin<<<dim3(cdiv(2*DI*DM, 256), 2), 256>>>(Wi, (size_t)2*DI*DM, 2*DI, DM,
                                                    wih, wil, (size_t)2*DI*DM, DM);
    split_rest<<<dim3((SEG0 + SEG1 + SEG2) / 256, 2), 256>>>(
        Wx, Wdt, Wo, wxh, wxl, wdh, wdl, woh, wol);

    const bf16* curh = x0h;
    const bf16* curl = x0l;
    for (int l = 0; l < 2; l++) {
        const float* cw_l  = cw   + (size_t)l * DI * 4;
        const float* cb_l  = cb   + (size_t)l * DI;
        const float* bdt_l = bdt  + (size_t)l * DI;
        const float* Al_l  = Alog + (size_t)l * DI * DSTATE;
        const float* Dp_l  = Dp   + (size_t)l * DI;

        dim3 blk(256);
        // in_proj: [8192 x 3072], K=768
        gemm_bf16x3<0><<<dim3(24, 64), blk, 2*STAGEB>>>(
            curh, curl, DM, wih + (size_t)l*2*DI*DM, wil + (size_t)l*2*DI*DM,
            nullptr, p_xz, 2*DI, nullptr, nullptr, 0, 0, DM);

        dim3 gc(SEQ / 32, DI / 32, BATCH);
        conv_silu_kernel<<<gc, dim3(32, 32)>>>(p_xz, cw_l, cb_l, xch, xcl, p_uT);

        // x_proj: [8192 x 176], K=1536; also emits (hi,lo) of cols<48 into dtA
        gemm_bf16x3<2><<<dim3(2, 64), blk, 2*STAGEB>>>(
            xch, xcl, DI, wxh + (size_t)l*XPDP*DI, wxl + (size_t)l*XPDP*DI,
            nullptr, p_xdbl, XPD, dah, dal, DTKP, DTR, DI);

        // dt TRANSPOSED: C^T[1536 x 8192] = Wdt[1536,64] * dtA[8192,64]^T
        gemm_bf16x3<1><<<dim3(64, 12), blk, 2*STAGEB>>>(
            wdh + (size_t)l*DI*DTKP, wdl + (size_t)l*DI*DTKP, DTKP,
            dah, dal, bdt_l, p_dtT, NTOK, nullptr, nullptr, 0, 0, DTKP);

        scan_kernel<<<dim3(DI / SCW, BATCH), 256, SC_SMEM>>>(
            p_dtT, p_uT, p_xdbl, Al_l, p_yT);

        gate_kernel<<<gc, dim3(32, 32)>>>(p_yT, p_uT, Dp_l, p_xz, gth, gtl);

        // out_proj: [8192 x 768], K=1536
        if (l == 0) {
            gemm_bf16x3<3><<<dim3(6, 64), blk, 2*STAGEB>>>(
                gth, gtl, DI, woh + (size_t)l*DM*DI, wol + (size_t)l*DM*DI,
                nullptr, nullptr, DM, x1h, x1l, DM, DM, DI);
            curh = x1h; curl = x1l;
        } else {
            gemm_bf16x3<0><<<dim3(6, 64), blk, 2*STAGEB>>>(
                gth, gtl, DI, woh + (size_t)l*DM*DI, wol + (size_t)l*DM*DI,
                nullptr, (float*)d_out, DM, nullptr, nullptr, 0, 0, DI);
        }
    }
}